// round 12
// baseline (speedup 1.0000x reference)
#include <cuda_runtime.h>
#include <math.h>

typedef unsigned long long u64;

#define BATCH 4096

__device__ float g_a0raw[BATCH*196];
__device__ float g_p2[BATCH*16*25];
__device__ float g_y3[BATCH*128];
__device__ float g_w1[576];
__device__ float g_w2[9216];
__device__ float g_w3t[51200];
__device__ float g_w4[1280];
__device__ float g_inv[4];
__device__ float g_bn1m[64], g_bn1i[64];
__device__ float g_bn2m[16], g_bn2i[16];
__device__ float2 g_pp1[64*512];
__device__ float2 g_pp2[16*1024];
__device__ unsigned g_cmn1[64], g_cmx1[64];
__device__ unsigned g_cmn2[16], g_cmx2[16];
__device__ unsigned g_mm[8];
__device__ float g_qmm[4];
__device__ unsigned g_cnt1, g_cnt2;

union F4U { float4 f; u64 u[2]; };

__device__ __forceinline__ unsigned fenc(float f){
    unsigned u = __float_as_uint(f);
    return (u & 0x80000000u) ? ~u : (u | 0x80000000u);
}
__device__ __forceinline__ float fdec(unsigned u){
    return (u & 0x80000000u) ? __uint_as_float(u & 0x7FFFFFFFu) : __uint_as_float(~u);
}
__device__ __forceinline__ u64 pack2(float a, float b){
    u64 r; asm("mov.b64 %0, {%1, %2};" : "=l"(r) : "f"(a), "f"(b)); return r;
}
__device__ __forceinline__ void fma2(u64 &d, u64 a, u64 b){
    asm("fma.rn.f32x2 %0, %1, %2, %0;" : "+l"(d) : "l"(a), "l"(b));
}
__device__ __forceinline__ u64 mul2(u64 a, u64 b){
    u64 r; asm("mul.rn.f32x2 %0, %1, %2;" : "=l"(r) : "l"(a), "l"(b)); return r;
}
__device__ __forceinline__ u64 add2(u64 a, u64 b){
    u64 r; asm("add.rn.f32x2 %0, %1, %2;" : "=l"(r) : "l"(a), "l"(b)); return r;
}
__device__ __forceinline__ float2 unpack2(u64 v){
    float2 f; asm("mov.b64 {%0, %1}, %2;" : "=f"(f.x), "=f"(f.y) : "l"(v)); return f;
}
__device__ __forceinline__ u64 mkO(u64 a, u64 b){
    float2 fa = unpack2(a); float2 fb = unpack2(b); return pack2(fa.y, fb.x);
}

#define QUANTA0(v) (__fmul_rn(__fadd_rn(rintf(__fmul_rn(__fsub_rn((v),mn),rsc)), zp), sc))

#define C1ROW(Earr, wa, wb, wc) do{ \
    _Pragma("unroll") \
    for (int j = 0; j < 6; j++){ \
        u64 _O = mkO(Earr[j], Earr[j+1]); \
        fma2(acc[j], Earr[j],   wa); \
        fma2(acc[j], _O,        wb); \
        fma2(acc[j], Earr[j+1], wc); \
    } }while(0)

#define LOADROW(Ap, r, E) do{ \
    const float2* _p = (const float2*)((Ap) + (r)*14); \
    _Pragma("unroll") \
    for (int j = 0; j < 7; j++){ float2 _v = _p[j]; E[j] = pack2(_v.x, _v.y); } }while(0)

__global__ void k_init(){
    int t = threadIdx.x;
    if (t < 8)  g_mm[t] = (t & 1) ? 0u : 0xFFFFFFFFu;
    if (t < 64){ g_cmn1[t] = 0xFFFFFFFFu; g_cmx1[t] = 0u; }
    if (t < 16){ g_cmn2[t] = 0xFFFFFFFFu; g_cmx2[t] = 0u; }
    if (t == 0){ g_cnt1 = 0u; g_cnt2 = 0u; }
}

/* ---- merged: blocks 0-3 weight-gen; blocks 4+ maxpool 28->14 + minmax ---- */
__global__ void k_pre(const float* __restrict__ x,
                      const float* s1,const float* g1,const float* a1,const float* b1,
                      const float* s2,const float* g2,const float* a2,const float* b2,
                      const float* s3,const float* g3,const float* a3,const float* b3,
                      const float* s4,const float* g4,const float* a4,const float* b4)
{
    __shared__ float red[1024];
    __shared__ unsigned hist[4][256];
    __shared__ unsigned sh_pref;
    __shared__ int sh_rank;
    __shared__ int ties[2048];
    __shared__ int ntie, Gtot, Cidx;
    __shared__ unsigned smn, smx;
    int t = threadIdx.x;

    if (blockIdx.x >= 4){
        if (t == 0){ smn = 0xFFFFFFFFu; smx = 0u; }
        __syncthreads();
        int idx = (blockIdx.x - 4)*1024 + t;       /* 401408 total */
        int b = idx / 98, rem = idx % 98, r = rem / 7, cq = rem % 7;
        const float4* p0 = (const float4*)&x[b*784 + (r*2)*28 + cq*4];
        const float4* p1 = (const float4*)&x[b*784 + (r*2+1)*28 + cq*4];
        float4 a = *p0, c = *p1;
        float o0 = fmaxf(fmaxf(a.x, a.y), fmaxf(c.x, c.y));
        float o1 = fmaxf(fmaxf(a.z, a.w), fmaxf(c.z, c.w));
        float2 o; o.x = o0; o.y = o1;
        *(float2*)&g_a0raw[b*196 + r*14 + cq*2] = o;
        unsigned e0 = fenc(o0), e1 = fenc(o1);
        atomicMin(&smn, min(e0, e1)); atomicMax(&smx, max(e0, e1));
        __syncthreads();
        if (t == 0){ atomicMin(&g_mm[0], smn); atomicMax(&g_mm[1], smx); }
        return;
    }

    int L = blockIdx.x;
    const float *sc, *sg, *h1, *h0; int n; float coeff;
    if (L == 0){ sc=s1; sg=g1; h1=a1; h0=b1; n=576;   coeff=0.666666667f; }
    else if (L == 1){ sc=s2; sg=g2; h1=a2; h0=b2; n=9216;  coeff=0.0833333333f; }
    else if (L == 2){ sc=s3; sg=g3; h1=a3; h0=b3; n=51200; coeff=0.1f; }
    else            { sc=s4; sg=g4; h1=a4; h0=b4; n=1280;  coeff=0.17677669529663689f; }

    int hg = t >> 8;
    float s = 0.f;
    for (int i = t; i < n; i += 1024) s += h1[i];
    red[t] = s; __syncthreads();
    for (int o = 512; o > 0; o >>= 1){ if (t < o) red[t] += red[t+o]; __syncthreads(); }
    if (t == 0) g_inv[L] = coeff / (red[0] / (float)n);

    unsigned pref = 0; int rank = n >> 1;
    for (int shift = 24; shift >= 0; shift -= 8){
        if (t < 256){ hist[0][t]=0; hist[1][t]=0; hist[2][t]=0; hist[3][t]=0; }
        __syncthreads();
        unsigned mask = (shift < 24) ? (0xFFFFFFFFu << (shift+8)) : 0u;
        for (int i = t; i < n; i += 1024){
            unsigned k = __float_as_uint(fabsf(sc[i]));
            if ((k & mask) == (pref & mask)) atomicAdd(&hist[hg][(k >> shift) & 255], 1u);
        }
        __syncthreads();
        if (t == 0){
            unsigned c = 0; int d = 0;
            for (; d < 255; d++){
                unsigned hd = hist[0][d]+hist[1][d]+hist[2][d]+hist[3][d];
                if (c + hd > (unsigned)rank) break; c += hd;
            }
            sh_pref = pref | ((unsigned)d << shift);
            sh_rank = rank - (int)c;
        }
        __syncthreads();
        pref = sh_pref; rank = sh_rank;
        __syncthreads();
    }
    unsigned thr = pref;
    if (t == 0){ ntie = 0; Gtot = 0; }
    __syncthreads();
    int g = 0;
    for (int i = t; i < n; i += 1024){
        unsigned k = __float_as_uint(fabsf(sc[i]));
        if (k > thr) g++;
        else if (k == thr){ int p = atomicAdd(&ntie, 1); if (p < 2048) ties[p] = i; }
    }
    atomicAdd(&Gtot, g);
    __syncthreads();
    if (t == 0){
        int E = ntie; if (E > 2048) E = 2048;
        for (int a = 1; a < E; a++){
            int v = ties[a]; int b2 = a - 1;
            while (b2 >= 0 && ties[b2] > v){ ties[b2+1] = ties[b2]; b2--; }
            ties[b2+1] = v;
        }
        int T1 = (n - (n >> 1)) - Gtot;
        if (T1 < 1) T1 = 1; if (T1 > E) T1 = E;
        Cidx = ties[E - T1];
    }
    __syncthreads();
    int C = Cidx;
    for (int i = t; i < n; i += 1024){
        unsigned k = __float_as_uint(fabsf(sc[i]));
        bool m = (k > thr) || (k == thr && i >= C);
        float val = sg[i] * (m ? h1[i] : h0[i]);
        if (L == 2) g_w3t[(i % 400)*128 + (i / 400)] = val;
        else if (L == 0) g_w1[i] = val;
        else if (L == 1) g_w2[i] = val;
        else g_w4[i] = val;
    }
}

/* ---- conv1 stats: 8 images/block, 512 threads; last block folds finq1 ---- */
__global__ void k_conv1s(const int* __restrict__ qb){
    __shared__ float a0s[8*196];
    __shared__ float rs[512], rq[512];
    __shared__ unsigned rmn[512], rmx[512];
    __shared__ unsigned isLast;
    int blk = blockIdx.x, t = threadIdx.x;   /* 512 */
    float mn = fdec(g_mm[0]), mx = fdec(g_mm[1]);
    float lv = (float)((1 << qb[0]) - 1);
    float sc = (mx - mn) / lv;
    float zp = floorf(mn / sc);
    float rsc = 1.0f / sc;
    for (int i = t; i < 1568; i += 512)
        a0s[i] = QUANTA0(g_a0raw[blk*1568 + i]);
    __syncthreads();
    int img = t >> 6, co = t & 63;
    u64 wp[9];
    #pragma unroll
    for (int k = 0; k < 9; k++){ float w = g_w1[co*9 + k]; wp[k] = pack2(w, w); }
    float inv = g_inv[0];
    u64 invp = pack2(inv, inv);
    const float* A = &a0s[img*196];
    u64 s2 = pack2(0.f, 0.f), q2 = s2;
    float fmn = 1e30f, fmx = -1e30f;

#define STATS1 do{ _Pragma("unroll") for (int j = 0; j < 6; j++){ \
        u64 y2 = mul2(acc[j], invp); \
        s2 = add2(s2, y2); fma2(q2, y2, y2); \
        float2 f = unpack2(y2); \
        fmn = fminf(fmn, fminf(f.x, f.y)); fmx = fmaxf(fmx, fmaxf(f.x, f.y)); }}while(0)

    u64 R0[7], R1[7], R2[7];
    LOADROW(A, 0, R0); LOADROW(A, 1, R1);
    #pragma unroll
    for (int pr3 = 0; pr3 < 12; pr3 += 3){
        { LOADROW(A, pr3+2, R2); u64 acc[6];
          #pragma unroll
          for (int j=0;j<6;j++) acc[j]=pack2(0.f,0.f);
          C1ROW(R0, wp[0],wp[1],wp[2]); C1ROW(R1, wp[3],wp[4],wp[5]); C1ROW(R2, wp[6],wp[7],wp[8]);
          STATS1; }
        { LOADROW(A, pr3+3, R0); u64 acc[6];
          #pragma unroll
          for (int j=0;j<6;j++) acc[j]=pack2(0.f,0.f);
          C1ROW(R1, wp[0],wp[1],wp[2]); C1ROW(R2, wp[3],wp[4],wp[5]); C1ROW(R0, wp[6],wp[7],wp[8]);
          STATS1; }
        { LOADROW(A, pr3+4, R1); u64 acc[6];
          #pragma unroll
          for (int j=0;j<6;j++) acc[j]=pack2(0.f,0.f);
          C1ROW(R2, wp[0],wp[1],wp[2]); C1ROW(R0, wp[3],wp[4],wp[5]); C1ROW(R1, wp[6],wp[7],wp[8]);
          STATS1; }
    }
#undef STATS1
    float2 fs = unpack2(s2), fq = unpack2(q2);
    rs[t] = fs.x + fs.y; rq[t] = fq.x + fq.y;
    rmn[t] = fenc(fmn); rmx[t] = fenc(fmx);
    __syncthreads();
    if (t < 64){
        float s = 0.f, q = 0.f;
        unsigned lmn = 0xFFFFFFFFu, lmx = 0u;
        #pragma unroll
        for (int im = 0; im < 8; im++){
            int i = im*64 + t;
            s += rs[i]; q += rq[i];
            lmn = min(lmn, rmn[i]); lmx = max(lmx, rmx[i]);
        }
        float2 pp; pp.x = s; pp.y = q;
        g_pp1[t*512 + blk] = pp;
        atomicMin(&g_cmn1[t], lmn); atomicMax(&g_cmx1[t], lmx);
    }
    /* last-block-done: fold finq1 */
    __threadfence();
    __syncthreads();
    if (t == 0){
        unsigned v = atomicAdd(&g_cnt1, 1u);
        isLast = (v == 511u) ? 1u : 0u;
    }
    __syncthreads();
    if (isLast){
        int c2 = t >> 3, sub = t & 7;
        float s = 0.f, q = 0.f;
        for (int i = sub; i < 512; i += 8){
            float2 pp = g_pp1[c2*512 + i];
            s += pp.x; q += pp.y;
        }
        #pragma unroll
        for (int o = 4; o > 0; o >>= 1){
            s += __shfl_down_sync(0xFFFFFFFFu, s, o);
            q += __shfl_down_sync(0xFFFFFFFFu, q, o);
        }
        __shared__ float sbm[64], sbi[64];
        if (sub == 0){
            float N = (float)(BATCH*144);
            float m = s / N; float v = q / N - m*m;
            float iv = 1.0f / sqrtf(v + 1e-5f);
            g_bn1m[c2] = m; g_bn1i[c2] = iv;
            sbm[c2] = m; sbi[c2] = iv;
        }
        __syncthreads();
        __shared__ float smn[64], smx[64];
        if (t < 64){
            float m = sbm[t], iv = sbi[t];
            smn[t] = fmaxf(__fmul_rn(__fsub_rn(fdec(g_cmn1[t]), m), iv), 0.f);
            smx[t] = fmaxf(__fmul_rn(__fsub_rn(fdec(g_cmx1[t]), m), iv), 0.f);
        }
        __syncthreads();
        for (int o = 32; o > 0; o >>= 1){
            if (t < o){ smn[t] = fminf(smn[t], smn[t+o]); smx[t] = fmaxf(smx[t], smx[t+o]); }
            __syncthreads();
        }
        if (t == 0){ g_qmm[0] = smn[0]; g_qmm[1] = smx[0]; }
    }
}

/* ---- conv2 fused, 640 threads (R9 form); last block folds finq2 ---- */
__global__ void __launch_bounds__(640, 1) k_conv2(const int* __restrict__ qb){
    extern __shared__ float sm[];
    float* in2 = sm;                 /* 4*9216 = 36864 */
    float* ws  = sm + 36864;         /* 16*577 =  9232 */
    float* a0s = sm + 46096;         /* 4*196  =   784 */
    float* w1s = sm + 46880;         /* 576 -> 47456 floats */
    int blk = blockIdx.x, t = threadIdx.x;   /* 640, 4 images */
    float mn = fdec(g_mm[0]), mx = fdec(g_mm[1]);
    float lv = (float)((1 << qb[0]) - 1);
    float sc = (mx - mn) / lv;
    float zp = floorf(mn / sc);
    float rsc = 1.0f / sc;
    for (int i = t; i < 784; i += 640)
        a0s[i] = QUANTA0(g_a0raw[blk*784 + i]);
    for (int i = t; i < 576; i += 640) w1s[i] = g_w1[i];
    for (int i = t; i < 9216; i += 640)
        ws[(i/576)*577 + (i%576)] = g_w2[i];
    __syncthreads();

    float qs1 = (g_qmm[1] - g_qmm[0]) / lv;
    float rq1 = 1.0f / qs1;
    if (t < 512){
        int img = t >> 7, co = (t >> 1) & 63, half = t & 1;
        u64 wp[9];
        #pragma unroll
        for (int k = 0; k < 9; k++){ float w = w1s[co*9 + k]; wp[k] = pack2(w, w); }
        float inv = g_inv[0];
        float m1 = g_bn1m[co], i1 = g_bn1i[co];
        const float* A = &a0s[img*196];
        float2* dst = (float2*)(in2 + img*9216 + co*144);
        int rb = half*6;

#define EMITB(PR) do{ _Pragma("unroll") for (int j = 0; j < 6; j++){ \
        float2 f = unpack2(acc[j]); \
        float y0 = __fmul_rn(f.x, inv), y1 = __fmul_rn(f.y, inv); \
        float u0 = fmaxf(__fmul_rn(__fsub_rn(y0, m1), i1), 0.f); \
        float u1 = fmaxf(__fmul_rn(__fsub_rn(y1, m1), i1), 0.f); \
        float2 o; \
        o.x = __fmul_rn(fminf(fmaxf(rintf(__fmul_rn(u0, rq1)), 0.f), lv), qs1); \
        o.y = __fmul_rn(fminf(fmaxf(rintf(__fmul_rn(u1, rq1)), 0.f), lv), qs1); \
        dst[(PR)*6 + j] = o; }}while(0)

        u64 R0[7], R1[7], R2[7];
        LOADROW(A, rb, R0); LOADROW(A, rb+1, R1);
        #pragma unroll
        for (int pr3 = 0; pr3 < 6; pr3 += 3){
            int base = rb + pr3;
            { LOADROW(A, base+2, R2); u64 acc[6];
              #pragma unroll
              for (int j=0;j<6;j++) acc[j]=pack2(0.f,0.f);
              C1ROW(R0, wp[0],wp[1],wp[2]); C1ROW(R1, wp[3],wp[4],wp[5]); C1ROW(R2, wp[6],wp[7],wp[8]);
              EMITB(base); }
            { LOADROW(A, base+3, R0); u64 acc[6];
              #pragma unroll
              for (int j=0;j<6;j++) acc[j]=pack2(0.f,0.f);
              C1ROW(R1, wp[0],wp[1],wp[2]); C1ROW(R2, wp[3],wp[4],wp[5]); C1ROW(R0, wp[6],wp[7],wp[8]);
              EMITB(base+1); }
            { LOADROW(A, base+4, R1); u64 acc[6];
              #pragma unroll
              for (int j=0;j<6;j++) acc[j]=pack2(0.f,0.f);
              C1ROW(R2, wp[0],wp[1],wp[2]); C1ROW(R0, wp[3],wp[4],wp[5]); C1ROW(R1, wp[6],wp[7],wp[8]);
              EMITB(base+2); }
        }
#undef EMITB
    }
    __syncthreads();

    /* phase C: warp w=(img,hp); lane: co=lane>>1, cih=lane&1 (32 ci each) */
    int w = t >> 5, lane = t & 31;
    int img = w / 5, hp = w % 5;
    int co = lane >> 1, cih = lane & 1;
    const float4* base4 = (const float4*)(in2 + img*9216);
    u64 acc2[2][5], accO[2][6];
    u64 zz = pack2(0.f, 0.f);
    #pragma unroll
    for (int o = 0; o < 2; o++){
        #pragma unroll
        for (int p = 0; p < 5; p++) acc2[o][p] = zz;
        #pragma unroll
        for (int p = 0; p < 6; p++) accO[o][p] = zz;
    }

    #pragma unroll 1
    for (int cc = 0; cc < 32; cc++){
        int ci = cc*2 + cih;
        const float* wr = &ws[co*577 + ci*9];
        u64 wp2[3][3];
        #pragma unroll
        for (int kh = 0; kh < 3; kh++)
            #pragma unroll
            for (int kw = 0; kw < 3; kw++){ float wv = wr[kh*3+kw]; wp2[kh][kw] = pack2(wv, wv); }
        #pragma unroll
        for (int lr = 0; lr < 4; lr++){
            int row = hp*2 + lr;
            F4U u0, u1, u2;
            u0.f = base4[ci*36 + row*3 + 0];
            u1.f = base4[ci*36 + row*3 + 1];
            u2.f = base4[ci*36 + row*3 + 2];
            u64 E[6];
            E[0]=u0.u[0]; E[1]=u0.u[1]; E[2]=u1.u[0]; E[3]=u1.u[1]; E[4]=u2.u[0]; E[5]=u2.u[1];
            if (lr <= 2){
                int kh = lr;
                #pragma unroll
                for (int p = 0; p < 5; p++) fma2(acc2[0][p], E[p],   wp2[kh][0]);
                #pragma unroll
                for (int p = 0; p < 6; p++) fma2(accO[0][p], E[p],   wp2[kh][1]);
                #pragma unroll
                for (int p = 0; p < 5; p++) fma2(acc2[0][p], E[p+1], wp2[kh][2]);
            }
            if (lr >= 1){
                int kh = lr - 1;
                #pragma unroll
                for (int p = 0; p < 5; p++) fma2(acc2[1][p], E[p],   wp2[kh][0]);
                #pragma unroll
                for (int p = 0; p < 6; p++) fma2(accO[1][p], E[p],   wp2[kh][1]);
                #pragma unroll
                for (int p = 0; p < 5; p++) fma2(acc2[1][p], E[p+1], wp2[kh][2]);
            }
        }
    }

    #pragma unroll
    for (int o = 0; o < 2; o++)
        #pragma unroll
        for (int p = 0; p < 5; p++)
            acc2[o][p] = add2(acc2[o][p], mkO(accO[o][p], accO[o][p+1]));

    #pragma unroll
    for (int o = 0; o < 2; o++)
        #pragma unroll
        for (int p = 0; p < 5; p++){
            u64 other = __shfl_xor_sync(0xFFFFFFFFu, acc2[o][p], 1);
            acc2[o][p] = add2(acc2[o][p], other);
        }

    float inv2 = g_inv[1];
    float s5 = 0.f, q5 = 0.f;
    unsigned mn5 = 0xFFFFFFFFu, mx5 = 0u;
    int pid = img*80 + co*5 + hp;
    if (cih == 0){
        int bimg = blk*4 + img;
        float* dstp = &g_p2[(bimg*16 + co)*25 + hp*5];
        #pragma unroll
        for (int p = 0; p < 5; p++){
            float2 a0 = unpack2(acc2[0][p]), a1 = unpack2(acc2[1][p]);
            float v = fmaxf(fmaxf(a0.x, a0.y), fmaxf(a1.x, a1.y)) * inv2;
            dstp[p] = v;
            s5 += v; q5 = fmaf(v, v, q5);
            unsigned e = fenc(v);
            mn5 = min(mn5, e); mx5 = max(mx5, e);
        }
    }
    __syncthreads();
    float* s_s = sm; float* s_q = sm + 320;
    unsigned* s_mn = (unsigned*)(sm + 640); unsigned* s_mx = (unsigned*)(sm + 960);
    if (cih == 0){ s_s[pid] = s5; s_q[pid] = q5; s_mn[pid] = mn5; s_mx[pid] = mx5; }
    __syncthreads();
    float* c_s = sm + 1280; float* c_q = sm + 1344;
    unsigned* c_mn = (unsigned*)(sm + 1408); unsigned* c_mx = (unsigned*)(sm + 1472);
    if (t < 64){
        int im = t >> 4, c = t & 15;
        int base = im*80 + c*5;
        float s = 0.f, q = 0.f;
        unsigned lmn = 0xFFFFFFFFu, lmx = 0u;
        #pragma unroll
        for (int h = 0; h < 5; h++){
            s += s_s[base + h]; q += s_q[base + h];
            lmn = min(lmn, s_mn[base + h]);
            lmx = max(lmx, s_mx[base + h]);
        }
        c_s[t] = s; c_q[t] = q; c_mn[t] = lmn; c_mx[t] = lmx;
    }
    __syncthreads();
    if (t < 16){
        float s = 0.f, q = 0.f;
        unsigned lmn = 0xFFFFFFFFu, lmx = 0u;
        #pragma unroll
        for (int im = 0; im < 4; im++){
            int i = im*16 + t;
            s += c_s[i]; q += c_q[i];
            lmn = min(lmn, c_mn[i]); lmx = max(lmx, c_mx[i]);
        }
        float2 pp; pp.x = s; pp.y = q;
        g_pp2[t*1024 + blk] = pp;
        atomicMin(&g_cmn2[t], lmn); atomicMax(&g_cmx2[t], lmx);
    }
    /* last-block-done: fold finq2 */
    __threadfence();
    __syncthreads();
    __shared__ unsigned isLast2;
    if (t == 0){
        unsigned v = atomicAdd(&g_cnt2, 1u);
        isLast2 = (v == 1023u) ? 1u : 0u;
    }
    __syncthreads();
    if (isLast2){
        __shared__ float sbm[16], sbi[16];
        __shared__ float qmn[16], qmx[16];
        if (t < 256){
            int c2 = t >> 4, sub = t & 15;
            float s = 0.f, q = 0.f;
            for (int i = sub; i < 1024; i += 16){
                float2 pp = g_pp2[c2*1024 + i];
                s += pp.x; q += pp.y;
            }
            #pragma unroll
            for (int o = 8; o > 0; o >>= 1){
                s += __shfl_down_sync(0xFFFFFFFFu, s, o);
                q += __shfl_down_sync(0xFFFFFFFFu, q, o);
            }
            if (sub == 0){
                float N = (float)(BATCH*25);
                float m = s / N; float v = q / N - m*m;
                float iv = 1.0f / sqrtf(v + 1e-5f);
                g_bn2m[c2] = m; g_bn2i[c2] = iv;
                sbm[c2] = m; sbi[c2] = iv;
            }
        }
        __syncthreads();
        if (t < 16){
            float m = sbm[t], iv = sbi[t];
            qmn[t] = fmaxf(__fmul_rn(__fsub_rn(fdec(g_cmn2[t]), m), iv), 0.f);
            qmx[t] = fmaxf(__fmul_rn(__fsub_rn(fdec(g_cmx2[t]), m), iv), 0.f);
        }
        __syncthreads();
        for (int o = 8; o > 0; o >>= 1){
            if (t < o){ qmn[t] = fminf(qmn[t], qmn[t+o]); qmx[t] = fmaxf(qmx[t], qmx[t+o]); }
            __syncthreads();
        }
        if (t == 0){ g_qmm[2] = qmn[0]; g_qmm[3] = qmx[0]; }
    }
}

/* ---- fc1 ---- */
__global__ void k_fc1(const int* __restrict__ qb){
    __shared__ float As[32][17];
    __shared__ float Bs[16][132];
    __shared__ unsigned smn, smx;
    int t = threadIdx.x;
    if (t == 0){ smn = 0xFFFFFFFFu; smx = 0u; }
    int rblk = blockIdx.x * 32;
    float lv = (float)((1 << qb[0]) - 1);
    float qs = (g_qmm[3] - g_qmm[2]) / lv;
    float rq = 1.0f / qs;
    float acc[4][4];
    #pragma unroll
    for (int i = 0; i < 4; i++)
        #pragma unroll
        for (int j = 0; j < 4; j++) acc[i][j] = 0.f;
    int rg = (t >> 5) * 4, c0 = t & 31;
    for (int kt = 0; kt < 400; kt += 16){
        for (int i = t; i < 512; i += 256){
            int row = i >> 4, kk = i & 15, k = kt + kk;
            int c = k / 25, rem = k % 25;
            float v = g_p2[((rblk + row)*16 + c)*25 + rem];
            float y = fmaxf(__fmul_rn(__fsub_rn(v, g_bn2m[c]), g_bn2i[c]), 0.f);
            As[row][kk] = fminf(fmaxf(rintf(y*rq), 0.f), lv) * qs;
        }
        for (int i = t; i < 2048; i += 256){
            int kk = i >> 7, nn = i & 127;
            Bs[kk][nn] = g_w3t[(kt + kk)*128 + nn];
        }
        __syncthreads();
        #pragma unroll
        for (int kk = 0; kk < 16; kk++){
            float a0 = As[rg][kk], a1 = As[rg+1][kk], a2 = As[rg+2][kk], a3 = As[rg+3][kk];
            float b0 = Bs[kk][c0], b1 = Bs[kk][c0+32], b2 = Bs[kk][c0+64], b3 = Bs[kk][c0+96];
            acc[0][0]=fmaf(a0,b0,acc[0][0]); acc[0][1]=fmaf(a0,b1,acc[0][1]);
            acc[0][2]=fmaf(a0,b2,acc[0][2]); acc[0][3]=fmaf(a0,b3,acc[0][3]);
            acc[1][0]=fmaf(a1,b0,acc[1][0]); acc[1][1]=fmaf(a1,b1,acc[1][1]);
            acc[1][2]=fmaf(a1,b2,acc[1][2]); acc[1][3]=fmaf(a1,b3,acc[1][3]);
            acc[2][0]=fmaf(a2,b0,acc[2][0]); acc[2][1]=fmaf(a2,b1,acc[2][1]);
            acc[2][2]=fmaf(a2,b2,acc[2][2]); acc[2][3]=fmaf(a2,b3,acc[2][3]);
            acc[3][0]=fmaf(a3,b0,acc[3][0]); acc[3][1]=fmaf(a3,b1,acc[3][1]);
            acc[3][2]=fmaf(a3,b2,acc[3][2]); acc[3][3]=fmaf(a3,b3,acc[3][3]);
        }
        __syncthreads();
    }
    float inv = g_inv[2];
    unsigned lmn = 0xFFFFFFFFu, lmx = 0u;
    #pragma unroll
    for (int ii = 0; ii < 4; ii++)
        #pragma unroll
        for (int jj = 0; jj < 4; jj++){
            float y = fmaxf(acc[ii][jj] * inv, 0.f);
            g_y3[(rblk + rg + ii)*128 + c0 + 32*jj] = y;
            unsigned e = fenc(y);
            lmn = min(lmn, e); lmx = max(lmx, e);
        }
    atomicMin(&smn, lmn); atomicMax(&smx, lmx);
    __syncthreads();
    if (t == 0){ atomicMin(&g_mm[6], smn); atomicMax(&g_mm[7], smx); }
}

/* ---- fc2 + log_softmax ---- */
__global__ void k_fc2(const int* __restrict__ qb, float* __restrict__ out){
    __shared__ float ws[1280];
    int t = threadIdx.x;
    for (int i = t; i < 1280; i += 256) ws[i] = g_w4[i];
    __syncthreads();
    float mn = fdec(g_mm[6]), mx = fdec(g_mm[7]);
    float lv = (float)((1 << qb[0]) - 1);
    float qs = (mx - mn) / lv;
    float rq = 1.0f / qs;
    float inv = g_inv[3];
    int warp = t / 32, lane = t % 32;
    int b = blockIdx.x * 8 + warp;
    float acc[10];
    #pragma unroll
    for (int o = 0; o < 10; o++) acc[o] = 0.f;
    for (int k = lane; k < 128; k += 32){
        float y = g_y3[b*128 + k];
        float q = fminf(fmaxf(rintf(y*rq), 0.f), lv) * qs;
        #pragma unroll
        for (int o = 0; o < 10; o++) acc[o] = fmaf(q, ws[o*128 + k], acc[o]);
    }
    #pragma unroll
    for (int off = 16; off > 0; off >>= 1)
        #pragma unroll
        for (int o = 0; o < 10; o++) acc[o] += __shfl_down_sync(0xFFFFFFFFu, acc[o], off);
    if (lane == 0){
        float l[10], m = -1e30f;
        #pragma unroll
        for (int o = 0; o < 10; o++){ l[o] = acc[o] * inv; m = fmaxf(m, l[o]); }
        float s = 0.f;
        #pragma unroll
        for (int o = 0; o < 10; o++) s += expf(l[o] - m);
        float ls = logf(s);
        #pragma unroll
        for (int o = 0; o < 10; o++) out[b*10 + o] = l[o] - m - ls;
    }
}

extern "C" void kernel_launch(void* const* d_in, const int* in_sizes, int n_in,
                              void* d_out, int out_size)
{
    const float* x   = (const float*)d_in[0];
    const float* sc1 = (const float*)d_in[1];
    const float* sg1 = (const float*)d_in[2];
    const float* h11 = (const float*)d_in[3];
    const float* h10 = (const float*)d_in[4];
    const float* sc2 = (const float*)d_in[5];
    const float* sg2 = (const float*)d_in[6];
    const float* h21 = (const float*)d_in[7];
    const float* h20 = (const float*)d_in[8];
    const float* sc3 = (const float*)d_in[9];
    const float* sg3 = (const float*)d_in[10];
    const float* h31 = (const float*)d_in[11];
    const float* h30 = (const float*)d_in[12];
    const float* sc4 = (const float*)d_in[13];
    const float* sg4 = (const float*)d_in[14];
    const float* h41 = (const float*)d_in[15];
    const float* h40 = (const float*)d_in[16];
    const int*   qb  = (const int*)d_in[17];
    float* out = (float*)d_out;

    cudaFuncSetAttribute(k_conv2, cudaFuncAttributeMaxDynamicSharedMemorySize, 189824);

    k_init<<<1, 128>>>();
    k_pre<<<4 + 392, 1024>>>(x,
                             sc1, sg1, h11, h10,
                             sc2, sg2, h21, h20,
                             sc3, sg3, h31, h30,
                             sc4, sg4, h41, h40);
    k_conv1s<<<512, 512>>>(qb);
    k_conv2<<<1024, 640, 189824>>>(qb);
    k_fc1<<<128, 256>>>(qb);
    k_fc2<<<512, 256>>>(qb, out);
}

// round 13
// speedup vs baseline: 1.0865x; 1.0865x over previous
#include <cuda_runtime.h>
#include <math.h>

typedef unsigned long long u64;

#define BATCH 4096

__device__ float g_a0raw[BATCH*196];
__device__ float g_p2[BATCH*16*25];
__device__ float g_y3[BATCH*128];
__device__ float g_w1[576];
__device__ float g_w2[9216];
__device__ float g_w3t[51200];
__device__ float g_w4[1280];
__device__ float g_inv[4];
__device__ float g_bn1m[64], g_bn1i[64];
__device__ float g_bn2m[16], g_bn2i[16];
__device__ float2 g_pp1[64*512];
__device__ float2 g_pp2[16*1024];
__device__ unsigned g_cmn1[64], g_cmx1[64];
__device__ unsigned g_cmn2[16], g_cmx2[16];
__device__ unsigned g_mm[8];
__device__ float g_qmm[4];

union F4U { float4 f; u64 u[2]; };

__device__ __forceinline__ unsigned fenc(float f){
    unsigned u = __float_as_uint(f);
    return (u & 0x80000000u) ? ~u : (u | 0x80000000u);
}
__device__ __forceinline__ float fdec(unsigned u){
    return (u & 0x80000000u) ? __uint_as_float(u & 0x7FFFFFFFu) : __uint_as_float(~u);
}
__device__ __forceinline__ u64 pack2(float a, float b){
    u64 r; asm("mov.b64 %0, {%1, %2};" : "=l"(r) : "f"(a), "f"(b)); return r;
}
__device__ __forceinline__ void fma2(u64 &d, u64 a, u64 b){
    asm("fma.rn.f32x2 %0, %1, %2, %0;" : "+l"(d) : "l"(a), "l"(b));
}
__device__ __forceinline__ u64 mul2(u64 a, u64 b){
    u64 r; asm("mul.rn.f32x2 %0, %1, %2;" : "=l"(r) : "l"(a), "l"(b)); return r;
}
__device__ __forceinline__ u64 add2(u64 a, u64 b){
    u64 r; asm("add.rn.f32x2 %0, %1, %2;" : "=l"(r) : "l"(a), "l"(b)); return r;
}
__device__ __forceinline__ float2 unpack2(u64 v){
    float2 f; asm("mov.b64 {%0, %1}, %2;" : "=f"(f.x), "=f"(f.y) : "l"(v)); return f;
}
__device__ __forceinline__ u64 mkO(u64 a, u64 b){
    float2 fa = unpack2(a); float2 fb = unpack2(b); return pack2(fa.y, fb.x);
}

#define QUANTA0(v) (__fmul_rn(__fadd_rn(rintf(__fmul_rn(__fsub_rn((v),mn),rsc)), zp), sc))

#define C1ROW(Earr, wa, wb, wc) do{ \
    _Pragma("unroll") \
    for (int j = 0; j < 6; j++){ \
        u64 _O = mkO(Earr[j], Earr[j+1]); \
        fma2(acc[j], Earr[j],   wa); \
        fma2(acc[j], _O,        wb); \
        fma2(acc[j], Earr[j+1], wc); \
    } }while(0)

#define LOADROW(Ap, r, E) do{ \
    const float2* _p = (const float2*)((Ap) + (r)*14); \
    _Pragma("unroll") \
    for (int j = 0; j < 7; j++){ float2 _v = _p[j]; E[j] = pack2(_v.x, _v.y); } }while(0)

__global__ void k_init(){
    int t = threadIdx.x;
    if (t < 8)  g_mm[t] = (t & 1) ? 0u : 0xFFFFFFFFu;
    if (t < 64){ g_cmn1[t] = 0xFFFFFFFFu; g_cmx1[t] = 0u; }
    if (t < 16){ g_cmn2[t] = 0xFFFFFFFFu; g_cmx2[t] = 0u; }
}

/* ---- merged: block 0 weight-gen L0 (w1); blocks 1+ maxpool 28->14 + minmax ---- */
__global__ void k_pre(const float* __restrict__ x,
                      const float* s1,const float* g1,const float* a1,const float* b1)
{
    __shared__ float red[1024];
    __shared__ unsigned hist[4][256];
    __shared__ unsigned sh_pref;
    __shared__ int sh_rank;
    __shared__ int ties[2048];
    __shared__ int ntie, Gtot, Cidx;
    __shared__ unsigned smn, smx;
    int t = threadIdx.x;

    if (blockIdx.x >= 1){
        if (t == 0){ smn = 0xFFFFFFFFu; smx = 0u; }
        __syncthreads();
        int idx = (blockIdx.x - 1)*1024 + t;       /* 401408 total */
        int b = idx / 98, rem = idx % 98, r = rem / 7, cq = rem % 7;
        const float4* p0 = (const float4*)&x[b*784 + (r*2)*28 + cq*4];
        const float4* p1 = (const float4*)&x[b*784 + (r*2+1)*28 + cq*4];
        float4 a = *p0, c = *p1;
        float o0 = fmaxf(fmaxf(a.x, a.y), fmaxf(c.x, c.y));
        float o1 = fmaxf(fmaxf(a.z, a.w), fmaxf(c.z, c.w));
        float2 o; o.x = o0; o.y = o1;
        *(float2*)&g_a0raw[b*196 + r*14 + cq*2] = o;
        unsigned e0 = fenc(o0), e1 = fenc(o1);
        atomicMin(&smn, min(e0, e1)); atomicMax(&smx, max(e0, e1));
        __syncthreads();
        if (t == 0){ atomicMin(&g_mm[0], smn); atomicMax(&g_mm[1], smx); }
        return;
    }

    /* wgen L0: n=576 */
    const float *sc = s1, *sg = g1, *h1 = a1, *h0 = b1;
    const int n = 576; const float coeff = 0.666666667f;
    int hg = t >> 8;
    float s = 0.f;
    for (int i = t; i < n; i += 1024) s += h1[i];
    red[t] = s; __syncthreads();
    for (int o = 512; o > 0; o >>= 1){ if (t < o) red[t] += red[t+o]; __syncthreads(); }
    if (t == 0) g_inv[0] = coeff / (red[0] / (float)n);

    unsigned pref = 0; int rank = n >> 1;
    for (int shift = 24; shift >= 0; shift -= 8){
        if (t < 256){ hist[0][t]=0; hist[1][t]=0; hist[2][t]=0; hist[3][t]=0; }
        __syncthreads();
        unsigned mask = (shift < 24) ? (0xFFFFFFFFu << (shift+8)) : 0u;
        for (int i = t; i < n; i += 1024){
            unsigned k = __float_as_uint(fabsf(sc[i]));
            if ((k & mask) == (pref & mask)) atomicAdd(&hist[hg][(k >> shift) & 255], 1u);
        }
        __syncthreads();
        if (t == 0){
            unsigned c = 0; int d = 0;
            for (; d < 255; d++){
                unsigned hd = hist[0][d]+hist[1][d]+hist[2][d]+hist[3][d];
                if (c + hd > (unsigned)rank) break; c += hd;
            }
            sh_pref = pref | ((unsigned)d << shift);
            sh_rank = rank - (int)c;
        }
        __syncthreads();
        pref = sh_pref; rank = sh_rank;
        __syncthreads();
    }
    unsigned thr = pref;
    if (t == 0){ ntie = 0; Gtot = 0; }
    __syncthreads();
    int g = 0;
    for (int i = t; i < n; i += 1024){
        unsigned k = __float_as_uint(fabsf(sc[i]));
        if (k > thr) g++;
        else if (k == thr){ int p = atomicAdd(&ntie, 1); if (p < 2048) ties[p] = i; }
    }
    atomicAdd(&Gtot, g);
    __syncthreads();
    if (t == 0){
        int E = ntie; if (E > 2048) E = 2048;
        for (int a = 1; a < E; a++){
            int v = ties[a]; int b2 = a - 1;
            while (b2 >= 0 && ties[b2] > v){ ties[b2+1] = ties[b2]; b2--; }
            ties[b2+1] = v;
        }
        int T1 = (n - (n >> 1)) - Gtot;
        if (T1 < 1) T1 = 1; if (T1 > E) T1 = E;
        Cidx = ties[E - T1];
    }
    __syncthreads();
    int C = Cidx;
    for (int i = t; i < n; i += 1024){
        unsigned k = __float_as_uint(fabsf(sc[i]));
        bool m = (k > thr) || (k == thr && i >= C);
        g_w1[i] = sg[i] * (m ? h1[i] : h0[i]);
    }
}

/* ---- conv1 stats (blocks 3..514; 8 img/block, 512 thr) +
        wgen L1/L2/L3 on blocks 0-2 (overlapped) ---- */
__global__ void k_conv1s(const int* __restrict__ qb,
                         const float* s2,const float* g2,const float* a2,const float* b2,
                         const float* s3,const float* g3,const float* a3,const float* b3,
                         const float* s4,const float* g4,const float* a4,const float* b4)
{
    int blk = blockIdx.x, t = threadIdx.x;   /* 512 */

    if (blk < 3){
        int L = blk + 1;
        const float *sc, *sg, *h1, *h0; int n; float coeff;
        if (L == 1){ sc=s2; sg=g2; h1=a2; h0=b2; n=9216;  coeff=0.0833333333f; }
        else if (L == 2){ sc=s3; sg=g3; h1=a3; h0=b3; n=51200; coeff=0.1f; }
        else            { sc=s4; sg=g4; h1=a4; h0=b4; n=1280;  coeff=0.17677669529663689f; }

        __shared__ float red[512];
        __shared__ unsigned hist[4][256];
        __shared__ unsigned sh_pref;
        __shared__ int sh_rank;
        __shared__ int ties[2048];
        __shared__ int ntie, Gtot, Cidx;
        int hg = t >> 7;

        float s = 0.f;
        for (int i = t; i < n; i += 512) s += h1[i];
        red[t] = s; __syncthreads();
        for (int o = 256; o > 0; o >>= 1){ if (t < o) red[t] += red[t+o]; __syncthreads(); }
        if (t == 0) g_inv[L] = coeff / (red[0] / (float)n);

        unsigned pref = 0; int rank = n >> 1;
        for (int shift = 24; shift >= 0; shift -= 8){
            if (t < 256){ hist[0][t]=0; hist[1][t]=0; hist[2][t]=0; hist[3][t]=0; }
            __syncthreads();
            unsigned mask = (shift < 24) ? (0xFFFFFFFFu << (shift+8)) : 0u;
            for (int i = t; i < n; i += 512){
                unsigned k = __float_as_uint(fabsf(sc[i]));
                if ((k & mask) == (pref & mask)) atomicAdd(&hist[hg][(k >> shift) & 255], 1u);
            }
            __syncthreads();
            if (t == 0){
                unsigned c = 0; int d = 0;
                for (; d < 255; d++){
                    unsigned hd = hist[0][d]+hist[1][d]+hist[2][d]+hist[3][d];
                    if (c + hd > (unsigned)rank) break; c += hd;
                }
                sh_pref = pref | ((unsigned)d << shift);
                sh_rank = rank - (int)c;
            }
            __syncthreads();
            pref = sh_pref; rank = sh_rank;
            __syncthreads();
        }
        unsigned thr = pref;
        if (t == 0){ ntie = 0; Gtot = 0; }
        __syncthreads();
        int g = 0;
        for (int i = t; i < n; i += 512){
            unsigned k = __float_as_uint(fabsf(sc[i]));
            if (k > thr) g++;
            else if (k == thr){ int p = atomicAdd(&ntie, 1); if (p < 2048) ties[p] = i; }
        }
        atomicAdd(&Gtot, g);
        __syncthreads();
        if (t == 0){
            int E = ntie; if (E > 2048) E = 2048;
            for (int a = 1; a < E; a++){
                int v = ties[a]; int b2i = a - 1;
                while (b2i >= 0 && ties[b2i] > v){ ties[b2i+1] = ties[b2i]; b2i--; }
                ties[b2i+1] = v;
            }
            int T1 = (n - (n >> 1)) - Gtot;
            if (T1 < 1) T1 = 1; if (T1 > E) T1 = E;
            Cidx = ties[E - T1];
        }
        __syncthreads();
        int C = Cidx;
        for (int i = t; i < n; i += 512){
            unsigned k = __float_as_uint(fabsf(sc[i]));
            bool m = (k > thr) || (k == thr && i >= C);
            float val = sg[i] * (m ? h1[i] : h0[i]);
            if (L == 2) g_w3t[(i % 400)*128 + (i / 400)] = val;
            else if (L == 1) g_w2[i] = val;
            else g_w4[i] = val;
        }
        return;
    }

    int cblk = blk - 3;
    __shared__ float a0s[8*196];
    __shared__ float rs[512], rq[512];
    __shared__ unsigned rmn[512], rmx[512];
    float mn = fdec(g_mm[0]), mx = fdec(g_mm[1]);
    float lv = (float)((1 << qb[0]) - 1);
    float sc = (mx - mn) / lv;
    float zp = floorf(mn / sc);
    float rsc = 1.0f / sc;
    for (int i = t; i < 1568; i += 512)
        a0s[i] = QUANTA0(g_a0raw[cblk*1568 + i]);
    __syncthreads();
    int img = t >> 6, co = t & 63;
    u64 wp[9];
    #pragma unroll
    for (int k = 0; k < 9; k++){ float w = g_w1[co*9 + k]; wp[k] = pack2(w, w); }
    float inv = g_inv[0];
    u64 invp = pack2(inv, inv);
    const float* A = &a0s[img*196];
    u64 s2v = pack2(0.f, 0.f), q2 = s2v;
    float fmn = 1e30f, fmx = -1e30f;

#define STATS1 do{ _Pragma("unroll") for (int j = 0; j < 6; j++){ \
        u64 y2 = mul2(acc[j], invp); \
        s2v = add2(s2v, y2); fma2(q2, y2, y2); \
        float2 f = unpack2(y2); \
        fmn = fminf(fmn, fminf(f.x, f.y)); fmx = fmaxf(fmx, fmaxf(f.x, f.y)); }}while(0)

    u64 R0[7], R1[7], R2[7];
    LOADROW(A, 0, R0); LOADROW(A, 1, R1);
    #pragma unroll
    for (int pr3 = 0; pr3 < 12; pr3 += 3){
        { LOADROW(A, pr3+2, R2); u64 acc[6];
          #pragma unroll
          for (int j=0;j<6;j++) acc[j]=pack2(0.f,0.f);
          C1ROW(R0, wp[0],wp[1],wp[2]); C1ROW(R1, wp[3],wp[4],wp[5]); C1ROW(R2, wp[6],wp[7],wp[8]);
          STATS1; }
        { LOADROW(A, pr3+3, R0); u64 acc[6];
          #pragma unroll
          for (int j=0;j<6;j++) acc[j]=pack2(0.f,0.f);
          C1ROW(R1, wp[0],wp[1],wp[2]); C1ROW(R2, wp[3],wp[4],wp[5]); C1ROW(R0, wp[6],wp[7],wp[8]);
          STATS1; }
        { LOADROW(A, pr3+4, R1); u64 acc[6];
          #pragma unroll
          for (int j=0;j<6;j++) acc[j]=pack2(0.f,0.f);
          C1ROW(R2, wp[0],wp[1],wp[2]); C1ROW(R0, wp[3],wp[4],wp[5]); C1ROW(R1, wp[6],wp[7],wp[8]);
          STATS1; }
    }
#undef STATS1
    float2 fs = unpack2(s2v), fq = unpack2(q2);
    rs[t] = fs.x + fs.y; rq[t] = fq.x + fq.y;
    rmn[t] = fenc(fmn); rmx[t] = fenc(fmx);
    __syncthreads();
    if (t < 64){
        float s = 0.f, q = 0.f;
        unsigned lmn = 0xFFFFFFFFu, lmx = 0u;
        #pragma unroll
        for (int im = 0; im < 8; im++){
            int i = im*64 + t;
            s += rs[i]; q += rq[i];
            lmn = min(lmn, rmn[i]); lmx = max(lmx, rmx[i]);
        }
        float2 pp; pp.x = s; pp.y = q;
        g_pp1[t*512 + cblk] = pp;
        atomicMin(&g_cmn1[t], lmn); atomicMax(&g_cmx1[t], lmx);
    }
}

/* ---- fused fin1 + q1: one block, 1024 threads, float2 partials ---- */
__global__ void k_finq1(){
    int t = threadIdx.x;
    int c = t >> 4, sub = t & 15;
    float s = 0.f, q = 0.f;
    for (int i = sub; i < 512; i += 16){
        float2 pp = g_pp1[c*512 + i];
        s += pp.x; q += pp.y;
    }
    #pragma unroll
    for (int o = 8; o > 0; o >>= 1){
        s += __shfl_down_sync(0xFFFFFFFFu, s, o);
        q += __shfl_down_sync(0xFFFFFFFFu, q, o);
    }
    __shared__ float sbm[64], sbi[64];
    if (sub == 0){
        float N = (float)(BATCH*144);
        float m = s / N; float v = q / N - m*m;
        float iv = 1.0f / sqrtf(v + 1e-5f);
        g_bn1m[c] = m; g_bn1i[c] = iv;
        sbm[c] = m; sbi[c] = iv;
    }
    __syncthreads();
    __shared__ float smn[64], smx[64];
    if (t < 64){
        float m = sbm[t], iv = sbi[t];
        smn[t] = fmaxf(__fmul_rn(__fsub_rn(fdec(g_cmn1[t]), m), iv), 0.f);
        smx[t] = fmaxf(__fmul_rn(__fsub_rn(fdec(g_cmx1[t]), m), iv), 0.f);
    }
    __syncthreads();
    for (int o = 32; o > 0; o >>= 1){
        if (t < o){ smn[t] = fminf(smn[t], smn[t+o]); smx[t] = fmaxf(smx[t], smx[t+o]); }
        __syncthreads();
    }
    if (t == 0){ g_qmm[0] = smn[0]; g_qmm[1] = smx[0]; }
}

/* ---- conv2 fused, 640 threads: phase B on 512 threads; phase C with
        padded 12-float weight rows (3x LDS.128) ---- */
__global__ void __launch_bounds__(640, 1) k_conv2(const int* __restrict__ qb){
    extern __shared__ float sm[];
    float* in2 = sm;                 /* 36864 floats            */
    float* ws  = sm + 36864;         /* 16*772 = 12352 floats   */
    float* a0s = sm + 49216;         /*   784 floats            */
    float* w1s = sm + 50000;         /*   576 -> 50576 floats   */
    int blk = blockIdx.x, t = threadIdx.x;   /* 640, 4 images */
    float mn = fdec(g_mm[0]), mx = fdec(g_mm[1]);
    float lv = (float)((1 << qb[0]) - 1);
    float sc = (mx - mn) / lv;
    float zp = floorf(mn / sc);
    float rsc = 1.0f / sc;
    for (int i = t; i < 784; i += 640)
        a0s[i] = QUANTA0(g_a0raw[blk*784 + i]);
    for (int i = t; i < 576; i += 640) w1s[i] = g_w1[i];
    for (int i = t; i < 9216; i += 640){
        int co = i/576, r = i%576;
        ws[co*772 + (r/9)*12 + (r%9)] = g_w2[i];
    }
    __syncthreads();

    float qs1 = (g_qmm[1] - g_qmm[0]) / lv;
    float rq1 = 1.0f / qs1;
    if (t < 512){
        int img = t >> 7, co = (t >> 1) & 63, half = t & 1;
        u64 wp[9];
        #pragma unroll
        for (int k = 0; k < 9; k++){ float w = w1s[co*9 + k]; wp[k] = pack2(w, w); }
        float inv = g_inv[0];
        float m1 = g_bn1m[co], i1 = g_bn1i[co];
        const float* A = &a0s[img*196];
        float2* dst = (float2*)(in2 + img*9216 + co*144);
        int rb = half*6;

#define EMITB(PR) do{ _Pragma("unroll") for (int j = 0; j < 6; j++){ \
        float2 f = unpack2(acc[j]); \
        float y0 = __fmul_rn(f.x, inv), y1 = __fmul_rn(f.y, inv); \
        float u0 = fmaxf(__fmul_rn(__fsub_rn(y0, m1), i1), 0.f); \
        float u1 = fmaxf(__fmul_rn(__fsub_rn(y1, m1), i1), 0.f); \
        float2 o; \
        o.x = __fmul_rn(fminf(fmaxf(rintf(__fmul_rn(u0, rq1)), 0.f), lv), qs1); \
        o.y = __fmul_rn(fminf(fmaxf(rintf(__fmul_rn(u1, rq1)), 0.f), lv), qs1); \
        dst[(PR)*6 + j] = o; }}while(0)

        u64 R0[7], R1[7], R2[7];
        LOADROW(A, rb, R0); LOADROW(A, rb+1, R1);
        #pragma unroll
        for (int pr3 = 0; pr3 < 6; pr3 += 3){
            int base = rb + pr3;
            { LOADROW(A, base+2, R2); u64 acc[6];
              #pragma unroll
              for (int j=0;j<6;j++) acc[j]=pack2(0.f,0.f);
              C1ROW(R0, wp[0],wp[1],wp[2]); C1ROW(R1, wp[3],wp[4],wp[5]); C1ROW(R2, wp[6],wp[7],wp[8]);
              EMITB(base); }
            { LOADROW(A, base+3, R0); u64 acc[6];
              #pragma unroll
              for (int j=0;j<6;j++) acc[j]=pack2(0.f,0.f);
              C1ROW(R1, wp[0],wp[1],wp[2]); C1ROW(R2, wp[3],wp[4],wp[5]); C1ROW(R0, wp[6],wp[7],wp[8]);
              EMITB(base+1); }
            { LOADROW(A, base+4, R1); u64 acc[6];
              #pragma unroll
              for (int j=0;j<6;j++) acc[j]=pack2(0.f,0.f);
              C1ROW(R2, wp[0],wp[1],wp[2]); C1ROW(R0, wp[3],wp[4],wp[5]); C1ROW(R1, wp[6],wp[7],wp[8]);
              EMITB(base+2); }
        }
#undef EMITB
    }
    __syncthreads();

    /* phase C: warp w=(img,hp); lane: co=lane>>1, cih=lane&1 (32 ci each) */
    int w = t >> 5, lane = t & 31;
    int img = w / 5, hp = w % 5;
    int co = lane >> 1, cih = lane & 1;
    const float4* base4 = (const float4*)(in2 + img*9216);
    u64 acc2[2][5], accO[2][6];
    u64 zz = pack2(0.f, 0.f);
    #pragma unroll
    for (int o = 0; o < 2; o++){
        #pragma unroll
        for (int p = 0; p < 5; p++) acc2[o][p] = zz;
        #pragma unroll
        for (int p = 0; p < 6; p++) accO[o][p] = zz;
    }

    #pragma unroll 1
    for (int cc = 0; cc < 32; cc++){
        int ci = cc*2 + cih;
        const float4* wr4 = (const float4*)(ws + co*772 + ci*12);
        float4 wa = wr4[0], wb = wr4[1], wc = wr4[2];
        u64 wp2[3][3];
        wp2[0][0]=pack2(wa.x,wa.x); wp2[0][1]=pack2(wa.y,wa.y); wp2[0][2]=pack2(wa.z,wa.z);
        wp2[1][0]=pack2(wa.w,wa.w); wp2[1][1]=pack2(wb.x,wb.x); wp2[1][2]=pack2(wb.y,wb.y);
        wp2[2][0]=pack2(wb.z,wb.z); wp2[2][1]=pack2(wb.w,wb.w); wp2[2][2]=pack2(wc.x,wc.x);
        #pragma unroll
        for (int lr = 0; lr < 4; lr++){
            int row = hp*2 + lr;
            F4U u0, u1, u2;
            u0.f = base4[ci*36 + row*3 + 0];
            u1.f = base4[ci*36 + row*3 + 1];
            u2.f = base4[ci*36 + row*3 + 2];
            u64 E[6];
            E[0]=u0.u[0]; E[1]=u0.u[1]; E[2]=u1.u[0]; E[3]=u1.u[1]; E[4]=u2.u[0]; E[5]=u2.u[1];
            if (lr <= 2){
                int kh = lr;
                #pragma unroll
                for (int p = 0; p < 5; p++) fma2(acc2[0][p], E[p],   wp2[kh][0]);
                #pragma unroll
                for (int p = 0; p < 6; p++) fma2(accO[0][p], E[p],   wp2[kh][1]);
                #pragma unroll
                for (int p = 0; p < 5; p++) fma2(acc2[0][p], E[p+1], wp2[kh][2]);
            }
            if (lr >= 1){
                int kh = lr - 1;
                #pragma unroll
                for (int p = 0; p < 5; p++) fma2(acc2[1][p], E[p],   wp2[kh][0]);
                #pragma unroll
                for (int p = 0; p < 6; p++) fma2(accO[1][p], E[p],   wp2[kh][1]);
                #pragma unroll
                for (int p = 0; p < 5; p++) fma2(acc2[1][p], E[p+1], wp2[kh][2]);
            }
        }
    }

    #pragma unroll
    for (int o = 0; o < 2; o++)
        #pragma unroll
        for (int p = 0; p < 5; p++)
            acc2[o][p] = add2(acc2[o][p], mkO(accO[o][p], accO[o][p+1]));

    #pragma unroll
    for (int o = 0; o < 2; o++)
        #pragma unroll
        for (int p = 0; p < 5; p++){
            u64 other = __shfl_xor_sync(0xFFFFFFFFu, acc2[o][p], 1);
            acc2[o][p] = add2(acc2[o][p], other);
        }

    float inv2 = g_inv[1];
    float s5 = 0.f, q5 = 0.f;
    unsigned mn5 = 0xFFFFFFFFu, mx5 = 0u;
    int pid = img*80 + co*5 + hp;
    if (cih == 0){
        int bimg = blk*4 + img;
        float* dstp = &g_p2[(bimg*16 + co)*25 + hp*5];
        #pragma unroll
        for (int p = 0; p < 5; p++){
            float2 a0 = unpack2(acc2[0][p]), a1 = unpack2(acc2[1][p]);
            float v = fmaxf(fmaxf(a0.x, a0.y), fmaxf(a1.x, a1.y)) * inv2;
            dstp[p] = v;
            s5 += v; q5 = fmaf(v, v, q5);
            unsigned e = fenc(v);
            mn5 = min(mn5, e); mx5 = max(mx5, e);
        }
    }
    __syncthreads();
    float* s_s = sm; float* s_q = sm + 320;
    unsigned* s_mn = (unsigned*)(sm + 640); unsigned* s_mx = (unsigned*)(sm + 960);
    if (cih == 0){ s_s[pid] = s5; s_q[pid] = q5; s_mn[pid] = mn5; s_mx[pid] = mx5; }
    __syncthreads();
    float* c_s = sm + 1280; float* c_q = sm + 1344;
    unsigned* c_mn = (unsigned*)(sm + 1408); unsigned* c_mx = (unsigned*)(sm + 1472);
    if (t < 64){
        int im = t >> 4, c = t & 15;
        int base = im*80 + c*5;
        float s = 0.f, q = 0.f;
        unsigned lmn = 0xFFFFFFFFu, lmx = 0u;
        #pragma unroll
        for (int h = 0; h < 5; h++){
            s += s_s[base + h]; q += s_q[base + h];
            lmn = min(lmn, s_mn[base + h]);
            lmx = max(lmx, s_mx[base + h]);
        }
        c_s[t] = s; c_q[t] = q; c_mn[t] = lmn; c_mx[t] = lmx;
    }
    __syncthreads();
    if (t < 16){
        float s = 0.f, q = 0.f;
        unsigned lmn = 0xFFFFFFFFu, lmx = 0u;
        #pragma unroll
        for (int im = 0; im < 4; im++){
            int i = im*16 + t;
            s += c_s[i]; q += c_q[i];
            lmn = min(lmn, c_mn[i]); lmx = max(lmx, c_mx[i]);
        }
        float2 pp; pp.x = s; pp.y = q;
        g_pp2[t*1024 + blk] = pp;
        atomicMin(&g_cmn2[t], lmn); atomicMax(&g_cmx2[t], lmx);
    }
}

/* ---- fused fin2 + q2: one block, 256 threads, float2 partials ---- */
__global__ void k_finq2(){
    int t = threadIdx.x;
    int c = t >> 4, sub = t & 15;
    float s = 0.f, q = 0.f;
    for (int i = sub; i < 1024; i += 16){
        float2 pp = g_pp2[c*1024 + i];
        s += pp.x; q += pp.y;
    }
    #pragma unroll
    for (int o = 8; o > 0; o >>= 1){
        s += __shfl_down_sync(0xFFFFFFFFu, s, o);
        q += __shfl_down_sync(0xFFFFFFFFu, q, o);
    }
    __shared__ float sbm[16], sbi[16];
    if (sub == 0){
        float N = (float)(BATCH*25);
        float m = s / N; float v = q / N - m*m;
        float iv = 1.0f / sqrtf(v + 1e-5f);
        g_bn2m[c] = m; g_bn2i[c] = iv;
        sbm[c] = m; sbi[c] = iv;
    }
    __syncthreads();
    __shared__ float smn[16], smx[16];
    if (t < 16){
        float m = sbm[t], iv = sbi[t];
        smn[t] = fmaxf(__fmul_rn(__fsub_rn(fdec(g_cmn2[t]), m), iv), 0.f);
        smx[t] = fmaxf(__fmul_rn(__fsub_rn(fdec(g_cmx2[t]), m), iv), 0.f);
    }
    __syncthreads();
    for (int o = 8; o > 0; o >>= 1){
        if (t < o){ smn[t] = fminf(smn[t], smn[t+o]); smx[t] = fmaxf(smx[t], smx[t+o]); }
        __syncthreads();
    }
    if (t == 0){ g_qmm[2] = smn[0]; g_qmm[3] = smx[0]; }
}

/* ---- fc1 ---- */
__global__ void k_fc1(const int* __restrict__ qb){
    __shared__ float As[32][17];
    __shared__ float Bs[16][132];
    __shared__ unsigned smn, smx;
    int t = threadIdx.x;
    if (t == 0){ smn = 0xFFFFFFFFu; smx = 0u; }
    int rblk = blockIdx.x * 32;
    float lv = (float)((1 << qb[0]) - 1);
    float qs = (g_qmm[3] - g_qmm[2]) / lv;
    float rq = 1.0f / qs;
    float acc[4][4];
    #pragma unroll
    for (int i = 0; i < 4; i++)
        #pragma unroll
        for (int j = 0; j < 4; j++) acc[i][j] = 0.f;
    int rg = (t >> 5) * 4, c0 = t & 31;
    for (int kt = 0; kt < 400; kt += 16){
        for (int i = t; i < 512; i += 256){
            int row = i >> 4, kk = i & 15, k = kt + kk;
            int c = k / 25, rem = k % 25;
            float v = g_p2[((rblk + row)*16 + c)*25 + rem];
            float y = fmaxf(__fmul_rn(__fsub_rn(v, g_bn2m[c]), g_bn2i[c]), 0.f);
            As[row][kk] = fminf(fmaxf(rintf(y*rq), 0.f), lv) * qs;
        }
        for (int i = t; i < 2048; i += 256){
            int kk = i >> 7, nn = i & 127;
            Bs[kk][nn] = g_w3t[(kt + kk)*128 + nn];
        }
        __syncthreads();
        #pragma unroll
        for (int kk = 0; kk < 16; kk++){
            float a0 = As[rg][kk], a1 = As[rg+1][kk], a2 = As[rg+2][kk], a3 = As[rg+3][kk];
            float b0 = Bs[kk][c0], b1 = Bs[kk][c0+32], b2 = Bs[kk][c0+64], b3 = Bs[kk][c0+96];
            acc[0][0]=fmaf(a0,b0,acc[0][0]); acc[0][1]=fmaf(a0,b1,acc[0][1]);
            acc[0][2]=fmaf(a0,b2,acc[0][2]); acc[0][3]=fmaf(a0,b3,acc[0][3]);
            acc[1][0]=fmaf(a1,b0,acc[1][0]); acc[1][1]=fmaf(a1,b1,acc[1][1]);
            acc[1][2]=fmaf(a1,b2,acc[1][2]); acc[1][3]=fmaf(a1,b3,acc[1][3]);
            acc[2][0]=fmaf(a2,b0,acc[2][0]); acc[2][1]=fmaf(a2,b1,acc[2][1]);
            acc[2][2]=fmaf(a2,b2,acc[2][2]); acc[2][3]=fmaf(a2,b3,acc[2][3]);
            acc[3][0]=fmaf(a3,b0,acc[3][0]); acc[3][1]=fmaf(a3,b1,acc[3][1]);
            acc[3][2]=fmaf(a3,b2,acc[3][2]); acc[3][3]=fmaf(a3,b3,acc[3][3]);
        }
        __syncthreads();
    }
    float inv = g_inv[2];
    unsigned lmn = 0xFFFFFFFFu, lmx = 0u;
    #pragma unroll
    for (int ii = 0; ii < 4; ii++)
        #pragma unroll
        for (int jj = 0; jj < 4; jj++){
            float y = fmaxf(acc[ii][jj] * inv, 0.f);
            g_y3[(rblk + rg + ii)*128 + c0 + 32*jj] = y;
            unsigned e = fenc(y);
            lmn = min(lmn, e); lmx = max(lmx, e);
        }
    atomicMin(&smn, lmn); atomicMax(&smx, lmx);
    __syncthreads();
    if (t == 0){ atomicMin(&g_mm[6], smn); atomicMax(&g_mm[7], smx); }
}

/* ---- fc2 + log_softmax ---- */
__global__ void k_fc2(const int* __restrict__ qb, float* __restrict__ out){
    __shared__ float ws[1280];
    int t = threadIdx.x;
    for (int i = t; i < 1280; i += 256) ws[i] = g_w4[i];
    __syncthreads();
    float mn = fdec(g_mm[6]), mx = fdec(g_mm[7]);
    float lv = (float)((1 << qb[0]) - 1);
    float qs = (mx - mn) / lv;
    float rq = 1.0f / qs;
    float inv = g_inv[3];
    int warp = t / 32, lane = t % 32;
    int b = blockIdx.x * 8 + warp;
    float acc[10];
    #pragma unroll
    for (int o = 0; o < 10; o++) acc[o] = 0.f;
    for (int k = lane; k < 128; k += 32){
        float y = g_y3[b*128 + k];
        float q = fminf(fmaxf(rintf(y*rq), 0.f), lv) * qs;
        #pragma unroll
        for (int o = 0; o < 10; o++) acc[o] = fmaf(q, ws[o*128 + k], acc[o]);
    }
    #pragma unroll
    for (int off = 16; off > 0; off >>= 1)
        #pragma unroll
        for (int o = 0; o < 10; o++) acc[o] += __shfl_down_sync(0xFFFFFFFFu, acc[o], off);
    if (lane == 0){
        float l[10], m = -1e30f;
        #pragma unroll
        for (int o = 0; o < 10; o++){ l[o] = acc[o] * inv; m = fmaxf(m, l[o]); }
        float s = 0.f;
        #pragma unroll
        for (int o = 0; o < 10; o++) s += expf(l[o] - m);
        float ls = logf(s);
        #pragma unroll
        for (int o = 0; o < 10; o++) out[b*10 + o] = l[o] - m - ls;
    }
}

extern "C" void kernel_launch(void* const* d_in, const int* in_sizes, int n_in,
                              void* d_out, int out_size)
{
    const float* x   = (const float*)d_in[0];
    const float* sc1 = (const float*)d_in[1];
    const float* sg1 = (const float*)d_in[2];
    const float* h11 = (const float*)d_in[3];
    const float* h10 = (const float*)d_in[4];
    const float* sc2 = (const float*)d_in[5];
    const float* sg2 = (const float*)d_in[6];
    const float* h21 = (const float*)d_in[7];
    const float* h20 = (const float*)d_in[8];
    const float* sc3 = (const float*)d_in[9];
    const float* sg3 = (const float*)d_in[10];
    const float* h31 = (const float*)d_in[11];
    const float* h30 = (const float*)d_in[12];
    const float* sc4 = (const float*)d_in[13];
    const float* sg4 = (const float*)d_in[14];
    const float* h41 = (const float*)d_in[15];
    const float* h40 = (const float*)d_in[16];
    const int*   qb  = (const int*)d_in[17];
    float* out = (float*)d_out;

    cudaFuncSetAttribute(k_conv2, cudaFuncAttributeMaxDynamicSharedMemorySize, 202304);

    k_init<<<1, 128>>>();
    k_pre<<<1 + 392, 1024>>>(x, sc1, sg1, h11, h10);
    k_conv1s<<<515, 512>>>(qb,
                           sc2, sg2, h21, h20,
                           sc3, sg3, h31, h30,
                           sc4, sg4, h41, h40);
    k_finq1<<<1, 1024>>>();
    k_conv2<<<1024, 640, 202304>>>(qb);
    k_finq2<<<1, 256>>>();
    k_fc1<<<128, 256>>>(qb);
    k_fc2<<<512, 256>>>(qb, out);
}

// round 14
// speedup vs baseline: 1.1275x; 1.0377x over previous
#include <cuda_runtime.h>
#include <math.h>

typedef unsigned long long u64;

#define BATCH 4096

__device__ float g_a0raw[BATCH*196];
__device__ float g_p2[BATCH*16*25];
__device__ float g_y3[BATCH*128];
__device__ float g_w1[576];
__device__ float g_w2[9216];
__device__ float g_w3t[51200];
__device__ float g_w4[1280];
__device__ float g_inv[4];
__device__ float g_bn1m[64], g_bn1i[64];
__device__ float g_bn2m[16], g_bn2i[16];
__device__ float2 g_pp1[64*512];
__device__ float2 g_pp2[16*1024];
__device__ unsigned g_cmn1[64], g_cmx1[64];
__device__ unsigned g_cmn2[16], g_cmx2[16];
__device__ unsigned g_mm[8];
__device__ float g_qmm[4];

union F4U { float4 f; u64 u[2]; };

__device__ __forceinline__ unsigned fenc(float f){
    unsigned u = __float_as_uint(f);
    return (u & 0x80000000u) ? ~u : (u | 0x80000000u);
}
__device__ __forceinline__ float fdec(unsigned u){
    return (u & 0x80000000u) ? __uint_as_float(u & 0x7FFFFFFFu) : __uint_as_float(~u);
}
__device__ __forceinline__ u64 pack2(float a, float b){
    u64 r; asm("mov.b64 %0, {%1, %2};" : "=l"(r) : "f"(a), "f"(b)); return r;
}
__device__ __forceinline__ void fma2(u64 &d, u64 a, u64 b){
    asm("fma.rn.f32x2 %0, %1, %2, %0;" : "+l"(d) : "l"(a), "l"(b));
}
__device__ __forceinline__ u64 mul2(u64 a, u64 b){
    u64 r; asm("mul.rn.f32x2 %0, %1, %2;" : "=l"(r) : "l"(a), "l"(b)); return r;
}
__device__ __forceinline__ u64 add2(u64 a, u64 b){
    u64 r; asm("add.rn.f32x2 %0, %1, %2;" : "=l"(r) : "l"(a), "l"(b)); return r;
}
__device__ __forceinline__ float2 unpack2(u64 v){
    float2 f; asm("mov.b64 {%0, %1}, %2;" : "=f"(f.x), "=f"(f.y) : "l"(v)); return f;
}
__device__ __forceinline__ u64 mkO(u64 a, u64 b){
    float2 fa = unpack2(a); float2 fb = unpack2(b); return pack2(fa.y, fb.x);
}

#define QUANTA0(v) (__fmul_rn(__fadd_rn(rintf(__fmul_rn(__fsub_rn((v),mn),rsc)), zp), sc))

#define C1ROW(Earr, wa, wb, wc) do{ \
    _Pragma("unroll") \
    for (int j = 0; j < 6; j++){ \
        u64 _O = mkO(Earr[j], Earr[j+1]); \
        fma2(acc[j], Earr[j],   wa); \
        fma2(acc[j], _O,        wb); \
        fma2(acc[j], Earr[j+1], wc); \
    } }while(0)

#define LOADROW(Ap, r, E) do{ \
    const float2* _p = (const float2*)((Ap) + (r)*14); \
    _Pragma("unroll") \
    for (int j = 0; j < 7; j++){ float2 _v = _p[j]; E[j] = pack2(_v.x, _v.y); } }while(0)

__global__ void k_init(){
    int t = threadIdx.x;
    if (t < 8)  g_mm[t] = (t & 1) ? 0u : 0xFFFFFFFFu;
    if (t < 64){ g_cmn1[t] = 0xFFFFFFFFu; g_cmx1[t] = 0u; }
    if (t < 16){ g_cmn2[t] = 0xFFFFFFFFu; g_cmx2[t] = 0u; }
}

/* ---- merged: blocks 0-3 weight-gen; blocks 4+ maxpool 28->14 + minmax ---- */
__global__ void k_pre(const float* __restrict__ x,
                      const float* s1,const float* g1,const float* a1,const float* b1,
                      const float* s2,const float* g2,const float* a2,const float* b2,
                      const float* s3,const float* g3,const float* a3,const float* b3,
                      const float* s4,const float* g4,const float* a4,const float* b4)
{
    __shared__ float red[1024];
    __shared__ unsigned hist[4][256];
    __shared__ unsigned sh_pref;
    __shared__ int sh_rank;
    __shared__ int ties[2048];
    __shared__ int ntie, Gtot, Cidx;
    __shared__ unsigned smn, smx;
    int t = threadIdx.x;

    if (blockIdx.x >= 4){
        if (t == 0){ smn = 0xFFFFFFFFu; smx = 0u; }
        __syncthreads();
        int idx = (blockIdx.x - 4)*1024 + t;       /* 401408 total */
        int b = idx / 98, rem = idx % 98, r = rem / 7, cq = rem % 7;
        const float4* p0 = (const float4*)&x[b*784 + (r*2)*28 + cq*4];
        const float4* p1 = (const float4*)&x[b*784 + (r*2+1)*28 + cq*4];
        float4 a = *p0, c = *p1;
        float o0 = fmaxf(fmaxf(a.x, a.y), fmaxf(c.x, c.y));
        float o1 = fmaxf(fmaxf(a.z, a.w), fmaxf(c.z, c.w));
        float2 o; o.x = o0; o.y = o1;
        *(float2*)&g_a0raw[b*196 + r*14 + cq*2] = o;
        unsigned e0 = fenc(o0), e1 = fenc(o1);
        atomicMin(&smn, min(e0, e1)); atomicMax(&smx, max(e0, e1));
        __syncthreads();
        if (t == 0){ atomicMin(&g_mm[0], smn); atomicMax(&g_mm[1], smx); }
        return;
    }

    int L = blockIdx.x;
    const float *sc, *sg, *h1, *h0; int n; float coeff;
    if (L == 0){ sc=s1; sg=g1; h1=a1; h0=b1; n=576;   coeff=0.666666667f; }
    else if (L == 1){ sc=s2; sg=g2; h1=a2; h0=b2; n=9216;  coeff=0.0833333333f; }
    else if (L == 2){ sc=s3; sg=g3; h1=a3; h0=b3; n=51200; coeff=0.1f; }
    else            { sc=s4; sg=g4; h1=a4; h0=b4; n=1280;  coeff=0.17677669529663689f; }

    int hg = t >> 8;
    float s = 0.f;
    for (int i = t; i < n; i += 1024) s += h1[i];
    red[t] = s; __syncthreads();
    for (int o = 512; o > 0; o >>= 1){ if (t < o) red[t] += red[t+o]; __syncthreads(); }
    if (t == 0) g_inv[L] = coeff / (red[0] / (float)n);

    unsigned pref = 0; int rank = n >> 1;
    for (int shift = 24; shift >= 0; shift -= 8){
        if (t < 256){ hist[0][t]=0; hist[1][t]=0; hist[2][t]=0; hist[3][t]=0; }
        __syncthreads();
        unsigned mask = (shift < 24) ? (0xFFFFFFFFu << (shift+8)) : 0u;
        for (int i = t; i < n; i += 1024){
            unsigned k = __float_as_uint(fabsf(sc[i]));
            if ((k & mask) == (pref & mask)) atomicAdd(&hist[hg][(k >> shift) & 255], 1u);
        }
        __syncthreads();
        if (t == 0){
            unsigned c = 0; int d = 0;
            for (; d < 255; d++){
                unsigned hd = hist[0][d]+hist[1][d]+hist[2][d]+hist[3][d];
                if (c + hd > (unsigned)rank) break; c += hd;
            }
            sh_pref = pref | ((unsigned)d << shift);
            sh_rank = rank - (int)c;
        }
        __syncthreads();
        pref = sh_pref; rank = sh_rank;
        __syncthreads();
    }
    unsigned thr = pref;
    if (t == 0){ ntie = 0; Gtot = 0; }
    __syncthreads();
    int g = 0;
    for (int i = t; i < n; i += 1024){
        unsigned k = __float_as_uint(fabsf(sc[i]));
        if (k > thr) g++;
        else if (k == thr){ int p = atomicAdd(&ntie, 1); if (p < 2048) ties[p] = i; }
    }
    atomicAdd(&Gtot, g);
    __syncthreads();
    if (t == 0){
        int E = ntie; if (E > 2048) E = 2048;
        for (int a = 1; a < E; a++){
            int v = ties[a]; int b2 = a - 1;
            while (b2 >= 0 && ties[b2] > v){ ties[b2+1] = ties[b2]; b2--; }
            ties[b2+1] = v;
        }
        int T1 = (n - (n >> 1)) - Gtot;
        if (T1 < 1) T1 = 1; if (T1 > E) T1 = E;
        Cidx = ties[E - T1];
    }
    __syncthreads();
    int C = Cidx;
    for (int i = t; i < n; i += 1024){
        unsigned k = __float_as_uint(fabsf(sc[i]));
        bool m = (k > thr) || (k == thr && i >= C);
        float val = sg[i] * (m ? h1[i] : h0[i]);
        if (L == 2) g_w3t[(i % 400)*128 + (i / 400)] = val;
        else if (L == 0) g_w1[i] = val;
        else if (L == 1) g_w2[i] = val;
        else g_w4[i] = val;
    }
}

/* ---- conv1 stats only: 8 images/block, 512 threads ---- */
__global__ void k_conv1s(const int* __restrict__ qb){
    __shared__ float a0s[8*196];
    __shared__ float rs[512], rq[512];
    __shared__ unsigned rmn[512], rmx[512];
    int blk = blockIdx.x, t = threadIdx.x;   /* 512 */
    float mn = fdec(g_mm[0]), mx = fdec(g_mm[1]);
    float lv = (float)((1 << qb[0]) - 1);
    float sc = (mx - mn) / lv;
    float zp = floorf(mn / sc);
    float rsc = 1.0f / sc;
    for (int i = t; i < 1568; i += 512)
        a0s[i] = QUANTA0(g_a0raw[blk*1568 + i]);
    __syncthreads();
    int img = t >> 6, co = t & 63;
    u64 wp[9];
    #pragma unroll
    for (int k = 0; k < 9; k++){ float w = g_w1[co*9 + k]; wp[k] = pack2(w, w); }
    float inv = g_inv[0];
    u64 invp = pack2(inv, inv);
    const float* A = &a0s[img*196];
    u64 s2 = pack2(0.f, 0.f), q2 = s2;
    float fmn = 1e30f, fmx = -1e30f;

#define STATS1 do{ _Pragma("unroll") for (int j = 0; j < 6; j++){ \
        u64 y2 = mul2(acc[j], invp); \
        s2 = add2(s2, y2); fma2(q2, y2, y2); \
        float2 f = unpack2(y2); \
        fmn = fminf(fmn, fminf(f.x, f.y)); fmx = fmaxf(fmx, fmaxf(f.x, f.y)); }}while(0)

    u64 R0[7], R1[7], R2[7];
    LOADROW(A, 0, R0); LOADROW(A, 1, R1);
    #pragma unroll
    for (int pr3 = 0; pr3 < 12; pr3 += 3){
        { LOADROW(A, pr3+2, R2); u64 acc[6];
          #pragma unroll
          for (int j=0;j<6;j++) acc[j]=pack2(0.f,0.f);
          C1ROW(R0, wp[0],wp[1],wp[2]); C1ROW(R1, wp[3],wp[4],wp[5]); C1ROW(R2, wp[6],wp[7],wp[8]);
          STATS1; }
        { LOADROW(A, pr3+3, R0); u64 acc[6];
          #pragma unroll
          for (int j=0;j<6;j++) acc[j]=pack2(0.f,0.f);
          C1ROW(R1, wp[0],wp[1],wp[2]); C1ROW(R2, wp[3],wp[4],wp[5]); C1ROW(R0, wp[6],wp[7],wp[8]);
          STATS1; }
        { LOADROW(A, pr3+4, R1); u64 acc[6];
          #pragma unroll
          for (int j=0;j<6;j++) acc[j]=pack2(0.f,0.f);
          C1ROW(R2, wp[0],wp[1],wp[2]); C1ROW(R0, wp[3],wp[4],wp[5]); C1ROW(R1, wp[6],wp[7],wp[8]);
          STATS1; }
    }
#undef STATS1
    float2 fs = unpack2(s2), fq = unpack2(q2);
    rs[t] = fs.x + fs.y; rq[t] = fq.x + fq.y;
    rmn[t] = fenc(fmn); rmx[t] = fenc(fmx);
    __syncthreads();
    if (t < 64){
        float s = 0.f, q = 0.f;
        unsigned lmn = 0xFFFFFFFFu, lmx = 0u;
        #pragma unroll
        for (int im = 0; im < 8; im++){
            int i = im*64 + t;
            s += rs[i]; q += rq[i];
            lmn = min(lmn, rmn[i]); lmx = max(lmx, rmx[i]);
        }
        float2 pp; pp.x = s; pp.y = q;
        g_pp1[t*512 + blk] = pp;
        atomicMin(&g_cmn1[t], lmn); atomicMax(&g_cmx1[t], lmx);
    }
}

/* ---- fused fin1 + q1: one block, 1024 threads, float2 partials ---- */
__global__ void k_finq1(){
    int t = threadIdx.x;
    int c = t >> 4, sub = t & 15;
    float s = 0.f, q = 0.f;
    for (int i = sub; i < 512; i += 16){
        float2 pp = g_pp1[c*512 + i];
        s += pp.x; q += pp.y;
    }
    #pragma unroll
    for (int o = 8; o > 0; o >>= 1){
        s += __shfl_down_sync(0xFFFFFFFFu, s, o);
        q += __shfl_down_sync(0xFFFFFFFFu, q, o);
    }
    __shared__ float sbm[64], sbi[64];
    if (sub == 0){
        float N = (float)(BATCH*144);
        float m = s / N; float v = q / N - m*m;
        float iv = 1.0f / sqrtf(v + 1e-5f);
        g_bn1m[c] = m; g_bn1i[c] = iv;
        sbm[c] = m; sbi[c] = iv;
    }
    __syncthreads();
    __shared__ float smn[64], smx[64];
    if (t < 64){
        float m = sbm[t], iv = sbi[t];
        smn[t] = fmaxf(__fmul_rn(__fsub_rn(fdec(g_cmn1[t]), m), iv), 0.f);
        smx[t] = fmaxf(__fmul_rn(__fsub_rn(fdec(g_cmx1[t]), m), iv), 0.f);
    }
    __syncthreads();
    for (int o = 32; o > 0; o >>= 1){
        if (t < o){ smn[t] = fminf(smn[t], smn[t+o]); smx[t] = fmaxf(smx[t], smx[t+o]); }
        __syncthreads();
    }
    if (t == 0){ g_qmm[0] = smn[0]; g_qmm[1] = smx[0]; }
}

/* ---- conv2 fused, 640 threads (R9 form); ws staging deferred into the
        phase-B-idle warps (t>=512) so it overlaps conv1 recompute ---- */
__global__ void __launch_bounds__(640, 1) k_conv2(const int* __restrict__ qb){
    extern __shared__ float sm[];
    float* in2 = sm;                 /* 4*9216 = 36864 */
    float* ws  = sm + 36864;         /* 16*577 =  9232 */
    float* a0s = sm + 46096;         /* 4*196  =   784 */
    float* w1s = sm + 46880;         /* 576 -> 47456 floats */
    int blk = blockIdx.x, t = threadIdx.x;   /* 640, 4 images */
    float mn = fdec(g_mm[0]), mx = fdec(g_mm[1]);
    float lv = (float)((1 << qb[0]) - 1);
    float sc = (mx - mn) / lv;
    float zp = floorf(mn / sc);
    float rsc = 1.0f / sc;
    /* phase A: stage only what phase B needs (a0s, w1s) */
    for (int i = t; i < 784; i += 640)
        a0s[i] = QUANTA0(g_a0raw[blk*784 + i]);
    for (int i = t; i < 576; i += 640) w1s[i] = g_w1[i];
    __syncthreads();

    float qs1 = (g_qmm[1] - g_qmm[0]) / lv;
    float rq1 = 1.0f / qs1;
    if (t < 512){
        int img = t >> 7, co = (t >> 1) & 63, half = t & 1;
        u64 wp[9];
        #pragma unroll
        for (int k = 0; k < 9; k++){ float w = w1s[co*9 + k]; wp[k] = pack2(w, w); }
        float inv = g_inv[0];
        float m1 = g_bn1m[co], i1 = g_bn1i[co];
        const float* A = &a0s[img*196];
        float2* dst = (float2*)(in2 + img*9216 + co*144);
        int rb = half*6;

#define EMITB(PR) do{ _Pragma("unroll") for (int j = 0; j < 6; j++){ \
        float2 f = unpack2(acc[j]); \
        float y0 = __fmul_rn(f.x, inv), y1 = __fmul_rn(f.y, inv); \
        float u0 = fmaxf(__fmul_rn(__fsub_rn(y0, m1), i1), 0.f); \
        float u1 = fmaxf(__fmul_rn(__fsub_rn(y1, m1), i1), 0.f); \
        float2 o; \
        o.x = __fmul_rn(fminf(fmaxf(rintf(__fmul_rn(u0, rq1)), 0.f), lv), qs1); \
        o.y = __fmul_rn(fminf(fmaxf(rintf(__fmul_rn(u1, rq1)), 0.f), lv), qs1); \
        dst[(PR)*6 + j] = o; }}while(0)

        u64 R0[7], R1[7], R2[7];
        LOADROW(A, rb, R0); LOADROW(A, rb+1, R1);
        #pragma unroll
        for (int pr3 = 0; pr3 < 6; pr3 += 3){
            int base = rb + pr3;
            { LOADROW(A, base+2, R2); u64 acc[6];
              #pragma unroll
              for (int j=0;j<6;j++) acc[j]=pack2(0.f,0.f);
              C1ROW(R0, wp[0],wp[1],wp[2]); C1ROW(R1, wp[3],wp[4],wp[5]); C1ROW(R2, wp[6],wp[7],wp[8]);
              EMITB(base); }
            { LOADROW(A, base+3, R0); u64 acc[6];
              #pragma unroll
              for (int j=0;j<6;j++) acc[j]=pack2(0.f,0.f);
              C1ROW(R1, wp[0],wp[1],wp[2]); C1ROW(R2, wp[3],wp[4],wp[5]); C1ROW(R0, wp[6],wp[7],wp[8]);
              EMITB(base+1); }
            { LOADROW(A, base+4, R1); u64 acc[6];
              #pragma unroll
              for (int j=0;j<6;j++) acc[j]=pack2(0.f,0.f);
              C1ROW(R2, wp[0],wp[1],wp[2]); C1ROW(R0, wp[3],wp[4],wp[5]); C1ROW(R1, wp[6],wp[7],wp[8]);
              EMITB(base+2); }
        }
#undef EMITB
    } else {
        /* warps 16-19: stage w2 into ws, overlapped with phase B */
        for (int i = t - 512; i < 9216; i += 128)
            ws[(i/576)*577 + (i%576)] = g_w2[i];
    }
    __syncthreads();

    /* phase C: warp w=(img,hp); lane: co=lane>>1, cih=lane&1 (32 ci each) */
    int w = t >> 5, lane = t & 31;
    int img = w / 5, hp = w % 5;
    int co = lane >> 1, cih = lane & 1;
    const float4* base4 = (const float4*)(in2 + img*9216);
    u64 acc2[2][5], accO[2][6];
    u64 zz = pack2(0.f, 0.f);
    #pragma unroll
    for (int o = 0; o < 2; o++){
        #pragma unroll
        for (int p = 0; p < 5; p++) acc2[o][p] = zz;
        #pragma unroll
        for (int p = 0; p < 6; p++) accO[o][p] = zz;
    }

    #pragma unroll 1
    for (int cc = 0; cc < 32; cc++){
        int ci = cc*2 + cih;
        const float* wr = &ws[co*577 + ci*9];
        u64 wp2[3][3];
        #pragma unroll
        for (int kh = 0; kh < 3; kh++)
            #pragma unroll
            for (int kw = 0; kw < 3; kw++){ float wv = wr[kh*3+kw]; wp2[kh][kw] = pack2(wv, wv); }
        #pragma unroll
        for (int lr = 0; lr < 4; lr++){
            int row = hp*2 + lr;
            F4U u0, u1, u2;
            u0.f = base4[ci*36 + row*3 + 0];
            u1.f = base4[ci*36 + row*3 + 1];
            u2.f = base4[ci*36 + row*3 + 2];
            u64 E[6];
            E[0]=u0.u[0]; E[1]=u0.u[1]; E[2]=u1.u[0]; E[3]=u1.u[1]; E[4]=u2.u[0]; E[5]=u2.u[1];
            if (lr <= 2){
                int kh = lr;
                #pragma unroll
                for (int p = 0; p < 5; p++) fma2(acc2[0][p], E[p],   wp2[kh][0]);
                #pragma unroll
                for (int p = 0; p < 6; p++) fma2(accO[0][p], E[p],   wp2[kh][1]);
                #pragma unroll
                for (int p = 0; p < 5; p++) fma2(acc2[0][p], E[p+1], wp2[kh][2]);
            }
            if (lr >= 1){
                int kh = lr - 1;
                #pragma unroll
                for (int p = 0; p < 5; p++) fma2(acc2[1][p], E[p],   wp2[kh][0]);
                #pragma unroll
                for (int p = 0; p < 6; p++) fma2(accO[1][p], E[p],   wp2[kh][1]);
                #pragma unroll
                for (int p = 0; p < 5; p++) fma2(acc2[1][p], E[p+1], wp2[kh][2]);
            }
        }
    }

    /* fold aux (kw=1) accumulators in with a single odd-pair shift */
    #pragma unroll
    for (int o = 0; o < 2; o++)
        #pragma unroll
        for (int p = 0; p < 5; p++)
            acc2[o][p] = add2(acc2[o][p], mkO(accO[o][p], accO[o][p+1]));

    /* combine ci halves across lane pairs */
    #pragma unroll
    for (int o = 0; o < 2; o++)
        #pragma unroll
        for (int p = 0; p < 5; p++){
            u64 other = __shfl_xor_sync(0xFFFFFFFFu, acc2[o][p], 1);
            acc2[o][p] = add2(acc2[o][p], other);
        }

    float inv2 = g_inv[1];
    float s5 = 0.f, q5 = 0.f;
    unsigned mn5 = 0xFFFFFFFFu, mx5 = 0u;
    int pid = img*80 + co*5 + hp;
    if (cih == 0){
        int bimg = blk*4 + img;
        float* dstp = &g_p2[(bimg*16 + co)*25 + hp*5];
        #pragma unroll
        for (int p = 0; p < 5; p++){
            float2 a0 = unpack2(acc2[0][p]), a1 = unpack2(acc2[1][p]);
            float v = fmaxf(fmaxf(a0.x, a0.y), fmaxf(a1.x, a1.y)) * inv2;
            dstp[p] = v;
            s5 += v; q5 = fmaf(v, v, q5);
            unsigned e = fenc(v);
            mn5 = min(mn5, e); mx5 = max(mx5, e);
        }
    }
    __syncthreads();
    float* s_s = sm; float* s_q = sm + 320;
    unsigned* s_mn = (unsigned*)(sm + 640); unsigned* s_mx = (unsigned*)(sm + 960);
    if (cih == 0){ s_s[pid] = s5; s_q[pid] = q5; s_mn[pid] = mn5; s_mx[pid] = mx5; }
    __syncthreads();
    float* c_s = sm + 1280; float* c_q = sm + 1344;
    unsigned* c_mn = (unsigned*)(sm + 1408); unsigned* c_mx = (unsigned*)(sm + 1472);
    if (t < 64){
        int im = t >> 4, c = t & 15;
        int base = im*80 + c*5;
        float s = 0.f, q = 0.f;
        unsigned lmn = 0xFFFFFFFFu, lmx = 0u;
        #pragma unroll
        for (int h = 0; h < 5; h++){
            s += s_s[base + h]; q += s_q[base + h];
            lmn = min(lmn, s_mn[base + h]);
            lmx = max(lmx, s_mx[base + h]);
        }
        c_s[t] = s; c_q[t] = q; c_mn[t] = lmn; c_mx[t] = lmx;
    }
    __syncthreads();
    if (t < 16){
        float s = 0.f, q = 0.f;
        unsigned lmn = 0xFFFFFFFFu, lmx = 0u;
        #pragma unroll
        for (int im = 0; im < 4; im++){
            int i = im*16 + t;
            s += c_s[i]; q += c_q[i];
            lmn = min(lmn, c_mn[i]); lmx = max(lmx, c_mx[i]);
        }
        float2 pp; pp.x = s; pp.y = q;
        g_pp2[t*1024 + blk] = pp;
        atomicMin(&g_cmn2[t], lmn); atomicMax(&g_cmx2[t], lmx);
    }
}

/* ---- fused fin2 + q2: one block, 256 threads, float2 partials ---- */
__global__ void k_finq2(){
    int t = threadIdx.x;
    int c = t >> 4, sub = t & 15;
    float s = 0.f, q = 0.f;
    for (int i = sub; i < 1024; i += 16){
        float2 pp = g_pp2[c*1024 + i];
        s += pp.x; q += pp.y;
    }
    #pragma unroll
    for (int o = 8; o > 0; o >>= 1){
        s += __shfl_down_sync(0xFFFFFFFFu, s, o);
        q += __shfl_down_sync(0xFFFFFFFFu, q, o);
    }
    __shared__ float sbm[16], sbi[16];
    if (sub == 0){
        float N = (float)(BATCH*25);
        float m = s / N; float v = q / N - m*m;
        float iv = 1.0f / sqrtf(v + 1e-5f);
        g_bn2m[c] = m; g_bn2i[c] = iv;
        sbm[c] = m; sbi[c] = iv;
    }
    __syncthreads();
    __shared__ float smn[16], smx[16];
    if (t < 16){
        float m = sbm[t], iv = sbi[t];
        smn[t] = fmaxf(__fmul_rn(__fsub_rn(fdec(g_cmn2[t]), m), iv), 0.f);
        smx[t] = fmaxf(__fmul_rn(__fsub_rn(fdec(g_cmx2[t]), m), iv), 0.f);
    }
    __syncthreads();
    for (int o = 8; o > 0; o >>= 1){
        if (t < o){ smn[t] = fminf(smn[t], smn[t+o]); smx[t] = fmaxf(smx[t], smx[t+o]); }
        __syncthreads();
    }
    if (t == 0){ g_qmm[2] = smn[0]; g_qmm[3] = smx[0]; }
}

/* ---- fc1 ---- */
__global__ void k_fc1(const int* __restrict__ qb){
    __shared__ float As[32][17];
    __shared__ float Bs[16][132];
    __shared__ unsigned smn, smx;
    int t = threadIdx.x;
    if (t == 0){ smn = 0xFFFFFFFFu; smx = 0u; }
    int rblk = blockIdx.x * 32;
    float lv = (float)((1 << qb[0]) - 1);
    float qs = (g_qmm[3] - g_qmm[2]) / lv;
    float rq = 1.0f / qs;
    float acc[4][4];
    #pragma unroll
    for (int i = 0; i < 4; i++)
        #pragma unroll
        for (int j = 0; j < 4; j++) acc[i][j] = 0.f;
    int rg = (t >> 5) * 4, c0 = t & 31;
    for (int kt = 0; kt < 400; kt += 16){
        for (int i = t; i < 512; i += 256){
            int row = i >> 4, kk = i & 15, k = kt + kk;
            int c = k / 25, rem = k % 25;
            float v = g_p2[((rblk + row)*16 + c)*25 + rem];
            float y = fmaxf(__fmul_rn(__fsub_rn(v, g_bn2m[c]), g_bn2i[c]), 0.f);
            As[row][kk] = fminf(fmaxf(rintf(y*rq), 0.f), lv) * qs;
        }
        for (int i = t; i < 2048; i += 256){
            int kk = i >> 7, nn = i & 127;
            Bs[kk][nn] = g_w3t[(kt + kk)*128 + nn];
        }
        __syncthreads();
        #pragma unroll
        for (int kk = 0; kk < 16; kk++){
            float a0 = As[rg][kk], a1 = As[rg+1][kk], a2 = As[rg+2][kk], a3 = As[rg+3][kk];
            float b0 = Bs[kk][c0], b1 = Bs[kk][c0+32], b2 = Bs[kk][c0+64], b3 = Bs[kk][c0+96];
            acc[0][0]=fmaf(a0,b0,acc[0][0]); acc[0][1]=fmaf(a0,b1,acc[0][1]);
            acc[0][2]=fmaf(a0,b2,acc[0][2]); acc[0][3]=fmaf(a0,b3,acc[0][3]);
            acc[1][0]=fmaf(a1,b0,acc[1][0]); acc[1][1]=fmaf(a1,b1,acc[1][1]);
            acc[1][2]=fmaf(a1,b2,acc[1][2]); acc[1][3]=fmaf(a1,b3,acc[1][3]);
            acc[2][0]=fmaf(a2,b0,acc[2][0]); acc[2][1]=fmaf(a2,b1,acc[2][1]);
            acc[2][2]=fmaf(a2,b2,acc[2][2]); acc[2][3]=fmaf(a2,b3,acc[2][3]);
            acc[3][0]=fmaf(a3,b0,acc[3][0]); acc[3][1]=fmaf(a3,b1,acc[3][1]);
            acc[3][2]=fmaf(a3,b2,acc[3][2]); acc[3][3]=fmaf(a3,b3,acc[3][3]);
        }
        __syncthreads();
    }
    float inv = g_inv[2];
    unsigned lmn = 0xFFFFFFFFu, lmx = 0u;
    #pragma unroll
    for (int ii = 0; ii < 4; ii++)
        #pragma unroll
        for (int jj = 0; jj < 4; jj++){
            float y = fmaxf(acc[ii][jj] * inv, 0.f);
            g_y3[(rblk + rg + ii)*128 + c0 + 32*jj] = y;
            unsigned e = fenc(y);
            lmn = min(lmn, e); lmx = max(lmx, e);
        }
    atomicMin(&smn, lmn); atomicMax(&smx, lmx);
    __syncthreads();
    if (t == 0){ atomicMin(&g_mm[6], smn); atomicMax(&g_mm[7], smx); }
}

/* ---- fc2 + log_softmax ---- */
__global__ void k_fc2(const int* __restrict__ qb, float* __restrict__ out){
    __shared__ float ws[1280];
    int t = threadIdx.x;
    for (int i = t; i < 1280; i += 256) ws[i] = g_w4[i];
    __syncthreads();
    float mn = fdec(g_mm[6]), mx = fdec(g_mm[7]);
    float lv = (float)((1 << qb[0]) - 1);
    float qs = (mx - mn) / lv;
    float rq = 1.0f / qs;
    float inv = g_inv[3];
    int warp = t / 32, lane = t % 32;
    int b = blockIdx.x * 8 + warp;
    float acc[10];
    #pragma unroll
    for (int o = 0; o < 10; o++) acc[o] = 0.f;
    for (int k = lane; k < 128; k += 32){
        float y = g_y3[b*128 + k];
        float q = fminf(fmaxf(rintf(y*rq), 0.f), lv) * qs;
        #pragma unroll
        for (int o = 0; o < 10; o++) acc[o] = fmaf(q, ws[o*128 + k], acc[o]);
    }
    #pragma unroll
    for (int off = 16; off > 0; off >>= 1)
        #pragma unroll
        for (int o = 0; o < 10; o++) acc[o] += __shfl_down_sync(0xFFFFFFFFu, acc[o], off);
    if (lane == 0){
        float l[10], m = -1e30f;
        #pragma unroll
        for (int o = 0; o < 10; o++){ l[o] = acc[o] * inv; m = fmaxf(m, l[o]); }
        float s = 0.f;
        #pragma unroll
        for (int o = 0; o < 10; o++) s += expf(l[o] - m);
        float ls = logf(s);
        #pragma unroll
        for (int o = 0; o < 10; o++) out[b*10 + o] = l[o] - m - ls;
    }
}

extern "C" void kernel_launch(void* const* d_in, const int* in_sizes, int n_in,
                              void* d_out, int out_size)
{
    const float* x   = (const float*)d_in[0];
    const float* sc1 = (const float*)d_in[1];
    const float* sg1 = (const float*)d_in[2];
    const float* h11 = (const float*)d_in[3];
    const float* h10 = (const float*)d_in[4];
    const float* sc2 = (const float*)d_in[5];
    const float* sg2 = (const float*)d_in[6];
    const float* h21 = (const float*)d_in[7];
    const float* h20 = (const float*)d_in[8];
    const float* sc3 = (const float*)d_in[9];
    const float* sg3 = (const float*)d_in[10];
    const float* h31 = (const float*)d_in[11];
    const float* h30 = (const float*)d_in[12];
    const float* sc4 = (const float*)d_in[13];
    const float* sg4 = (const float*)d_in[14];
    const float* h41 = (const float*)d_in[15];
    const float* h40 = (const float*)d_in[16];
    const int*   qb  = (const int*)d_in[17];
    float* out = (float*)d_out;

    cudaFuncSetAttribute(k_conv2, cudaFuncAttributeMaxDynamicSharedMemorySize, 189824);

    k_init<<<1, 128>>>();
    k_pre<<<4 + 392, 1024>>>(x,
                             sc1, sg1, h11, h10,
                             sc2, sg2, h21, h20,
                             sc3, sg3, h31, h30,
                             sc4, sg4, h41, h40);
    k_conv1s<<<512, 512>>>(qb);
    k_finq1<<<1, 1024>>>();
    k_conv2<<<1024, 640, 189824>>>(qb);
    k_finq2<<<1, 256>>>();
    k_fc1<<<128, 256>>>(qb);
    k_fc2<<<512, 256>>>(qb, out);
}

// round 15
// speedup vs baseline: 1.2812x; 1.1364x over previous
#include <cuda_runtime.h>
#include <math.h>

typedef unsigned long long u64;

#define BATCH 4096

__device__ float g_a0raw[BATCH*196];
__device__ float g_p2[BATCH*16*25];
__device__ float g_y3[BATCH*128];
__device__ float g_w1[576];
__device__ float g_w2[9216];
__device__ float g_w3t[51200];
__device__ float g_w4[1280];
__device__ float g_inv[4];
__device__ float g_bn1m[64], g_bn1i[64];
__device__ float g_bn2m[16], g_bn2i[16];
__device__ float2 g_pp1[64*512];
__device__ float2 g_pp2[16*1024];
__device__ unsigned g_cmn1[64], g_cmx1[64];
__device__ unsigned g_cmn2[16], g_cmx2[16];
__device__ unsigned g_mm[8];
__device__ float g_qmm[4];

union F4U { float4 f; u64 u[2]; };

__device__ __forceinline__ unsigned fenc(float f){
    unsigned u = __float_as_uint(f);
    return (u & 0x80000000u) ? ~u : (u | 0x80000000u);
}
__device__ __forceinline__ float fdec(unsigned u){
    return (u & 0x80000000u) ? __uint_as_float(u & 0x7FFFFFFFu) : __uint_as_float(~u);
}
__device__ __forceinline__ u64 pack2(float a, float b){
    u64 r; asm("mov.b64 %0, {%1, %2};" : "=l"(r) : "f"(a), "f"(b)); return r;
}
__device__ __forceinline__ void fma2(u64 &d, u64 a, u64 b){
    asm("fma.rn.f32x2 %0, %1, %2, %0;" : "+l"(d) : "l"(a), "l"(b));
}
__device__ __forceinline__ u64 mul2(u64 a, u64 b){
    u64 r; asm("mul.rn.f32x2 %0, %1, %2;" : "=l"(r) : "l"(a), "l"(b)); return r;
}
__device__ __forceinline__ u64 add2(u64 a, u64 b){
    u64 r; asm("add.rn.f32x2 %0, %1, %2;" : "=l"(r) : "l"(a), "l"(b)); return r;
}
__device__ __forceinline__ float2 unpack2(u64 v){
    float2 f; asm("mov.b64 {%0, %1}, %2;" : "=f"(f.x), "=f"(f.y) : "l"(v)); return f;
}
__device__ __forceinline__ u64 mkO(u64 a, u64 b){
    float2 fa = unpack2(a); float2 fb = unpack2(b); return pack2(fa.y, fb.x);
}

#define QUANTA0(v) (__fmul_rn(__fadd_rn(rintf(__fmul_rn(__fsub_rn((v),mn),rsc)), zp), sc))

#define C1ROW(Earr, wa, wb, wc) do{ \
    _Pragma("unroll") \
    for (int j = 0; j < 6; j++){ \
        u64 _O = mkO(Earr[j], Earr[j+1]); \
        fma2(acc[j], Earr[j],   wa); \
        fma2(acc[j], _O,        wb); \
        fma2(acc[j], Earr[j+1], wc); \
    } }while(0)

#define LOADROW(Ap, r, E) do{ \
    const float2* _p = (const float2*)((Ap) + (r)*14); \
    _Pragma("unroll") \
    for (int j = 0; j < 7; j++){ float2 _v = _p[j]; E[j] = pack2(_v.x, _v.y); } }while(0)

__global__ void k_init(){
    int t = threadIdx.x;
    if (t < 8)  g_mm[t] = (t & 1) ? 0u : 0xFFFFFFFFu;
    if (t < 64){ g_cmn1[t] = 0xFFFFFFFFu; g_cmx1[t] = 0u; }
    if (t < 16){ g_cmn2[t] = 0xFFFFFFFFu; g_cmx2[t] = 0u; }
}

/* ---- merged: blocks 0-1 weight-gen L0/L1; blocks 2+ maxpool 28->14 + minmax ---- */
__global__ void k_pre(const float* __restrict__ x,
                      const float* s1,const float* g1,const float* a1,const float* b1,
                      const float* s2,const float* g2,const float* a2,const float* b2)
{
    __shared__ float red[1024];
    __shared__ unsigned hist[4][256];
    __shared__ unsigned sh_pref;
    __shared__ int sh_rank;
    __shared__ int ties[2048];
    __shared__ int ntie, Gtot, Cidx;
    __shared__ unsigned smn, smx;
    int t = threadIdx.x;

    if (blockIdx.x >= 2){
        if (t == 0){ smn = 0xFFFFFFFFu; smx = 0u; }
        __syncthreads();
        int idx = (blockIdx.x - 2)*1024 + t;       /* 401408 total */
        int b = idx / 98, rem = idx % 98, r = rem / 7, cq = rem % 7;
        const float4* p0 = (const float4*)&x[b*784 + (r*2)*28 + cq*4];
        const float4* p1 = (const float4*)&x[b*784 + (r*2+1)*28 + cq*4];
        float4 a = *p0, c = *p1;
        float o0 = fmaxf(fmaxf(a.x, a.y), fmaxf(c.x, c.y));
        float o1 = fmaxf(fmaxf(a.z, a.w), fmaxf(c.z, c.w));
        float2 o; o.x = o0; o.y = o1;
        *(float2*)&g_a0raw[b*196 + r*14 + cq*2] = o;
        unsigned e0 = fenc(o0), e1 = fenc(o1);
        atomicMin(&smn, min(e0, e1)); atomicMax(&smx, max(e0, e1));
        __syncthreads();
        if (t == 0){ atomicMin(&g_mm[0], smn); atomicMax(&g_mm[1], smx); }
        return;
    }

    int L = blockIdx.x;
    const float *sc, *sg, *h1, *h0; int n; float coeff;
    if (L == 0){ sc=s1; sg=g1; h1=a1; h0=b1; n=576;   coeff=0.666666667f; }
    else       { sc=s2; sg=g2; h1=a2; h0=b2; n=9216;  coeff=0.0833333333f; }

    int hg = t >> 8;
    float s = 0.f;
    for (int i = t; i < n; i += 1024) s += h1[i];
    red[t] = s; __syncthreads();
    for (int o = 512; o > 0; o >>= 1){ if (t < o) red[t] += red[t+o]; __syncthreads(); }
    if (t == 0) g_inv[L] = coeff / (red[0] / (float)n);

    unsigned pref = 0; int rank = n >> 1;
    for (int shift = 24; shift >= 0; shift -= 8){
        if (t < 256){ hist[0][t]=0; hist[1][t]=0; hist[2][t]=0; hist[3][t]=0; }
        __syncthreads();
        unsigned mask = (shift < 24) ? (0xFFFFFFFFu << (shift+8)) : 0u;
        for (int i = t; i < n; i += 1024){
            unsigned k = __float_as_uint(fabsf(sc[i]));
            if ((k & mask) == (pref & mask)) atomicAdd(&hist[hg][(k >> shift) & 255], 1u);
        }
        __syncthreads();
        if (t == 0){
            unsigned c = 0; int d = 0;
            for (; d < 255; d++){
                unsigned hd = hist[0][d]+hist[1][d]+hist[2][d]+hist[3][d];
                if (c + hd > (unsigned)rank) break; c += hd;
            }
            sh_pref = pref | ((unsigned)d << shift);
            sh_rank = rank - (int)c;
        }
        __syncthreads();
        pref = sh_pref; rank = sh_rank;
        __syncthreads();
    }
    unsigned thr = pref;
    if (t == 0){ ntie = 0; Gtot = 0; }
    __syncthreads();
    int g = 0;
    for (int i = t; i < n; i += 1024){
        unsigned k = __float_as_uint(fabsf(sc[i]));
        if (k > thr) g++;
        else if (k == thr){ int p = atomicAdd(&ntie, 1); if (p < 2048) ties[p] = i; }
    }
    atomicAdd(&Gtot, g);
    __syncthreads();
    if (t == 0){
        int E = ntie; if (E > 2048) E = 2048;
        for (int a = 1; a < E; a++){
            int v = ties[a]; int b2 = a - 1;
            while (b2 >= 0 && ties[b2] > v){ ties[b2+1] = ties[b2]; b2--; }
            ties[b2+1] = v;
        }
        int T1 = (n - (n >> 1)) - Gtot;
        if (T1 < 1) T1 = 1; if (T1 > E) T1 = E;
        Cidx = ties[E - T1];
    }
    __syncthreads();
    int C = Cidx;
    for (int i = t; i < n; i += 1024){
        unsigned k = __float_as_uint(fabsf(sc[i]));
        bool m = (k > thr) || (k == thr && i >= C);
        float val = sg[i] * (m ? h1[i] : h0[i]);
        if (L == 0) g_w1[i] = val;
        else g_w2[i] = val;
    }
}

/* ---- conv1 stats only: 8 images/block, 512 threads ---- */
__global__ void k_conv1s(const int* __restrict__ qb){
    __shared__ float a0s[8*196];
    __shared__ float rs[512], rq[512];
    __shared__ unsigned rmn[512], rmx[512];
    int blk = blockIdx.x, t = threadIdx.x;   /* 512 */
    float mn = fdec(g_mm[0]), mx = fdec(g_mm[1]);
    float lv = (float)((1 << qb[0]) - 1);
    float sc = (mx - mn) / lv;
    float zp = floorf(mn / sc);
    float rsc = 1.0f / sc;
    for (int i = t; i < 1568; i += 512)
        a0s[i] = QUANTA0(g_a0raw[blk*1568 + i]);
    __syncthreads();
    int img = t >> 6, co = t & 63;
    u64 wp[9];
    #pragma unroll
    for (int k = 0; k < 9; k++){ float w = g_w1[co*9 + k]; wp[k] = pack2(w, w); }
    float inv = g_inv[0];
    u64 invp = pack2(inv, inv);
    const float* A = &a0s[img*196];
    u64 s2 = pack2(0.f, 0.f), q2 = s2;
    float fmn = 1e30f, fmx = -1e30f;

#define STATS1 do{ _Pragma("unroll") for (int j = 0; j < 6; j++){ \
        u64 y2 = mul2(acc[j], invp); \
        s2 = add2(s2, y2); fma2(q2, y2, y2); \
        float2 f = unpack2(y2); \
        fmn = fminf(fmn, fminf(f.x, f.y)); fmx = fmaxf(fmx, fmaxf(f.x, f.y)); }}while(0)

    u64 R0[7], R1[7], R2[7];
    LOADROW(A, 0, R0); LOADROW(A, 1, R1);
    #pragma unroll
    for (int pr3 = 0; pr3 < 12; pr3 += 3){
        { LOADROW(A, pr3+2, R2); u64 acc[6];
          #pragma unroll
          for (int j=0;j<6;j++) acc[j]=pack2(0.f,0.f);
          C1ROW(R0, wp[0],wp[1],wp[2]); C1ROW(R1, wp[3],wp[4],wp[5]); C1ROW(R2, wp[6],wp[7],wp[8]);
          STATS1; }
        { LOADROW(A, pr3+3, R0); u64 acc[6];
          #pragma unroll
          for (int j=0;j<6;j++) acc[j]=pack2(0.f,0.f);
          C1ROW(R1, wp[0],wp[1],wp[2]); C1ROW(R2, wp[3],wp[4],wp[5]); C1ROW(R0, wp[6],wp[7],wp[8]);
          STATS1; }
        { LOADROW(A, pr3+4, R1); u64 acc[6];
          #pragma unroll
          for (int j=0;j<6;j++) acc[j]=pack2(0.f,0.f);
          C1ROW(R2, wp[0],wp[1],wp[2]); C1ROW(R0, wp[3],wp[4],wp[5]); C1ROW(R1, wp[6],wp[7],wp[8]);
          STATS1; }
    }
#undef STATS1
    float2 fs = unpack2(s2), fq = unpack2(q2);
    rs[t] = fs.x + fs.y; rq[t] = fq.x + fq.y;
    rmn[t] = fenc(fmn); rmx[t] = fenc(fmx);
    __syncthreads();
    if (t < 64){
        float s = 0.f, q = 0.f;
        unsigned lmn = 0xFFFFFFFFu, lmx = 0u;
        #pragma unroll
        for (int im = 0; im < 8; im++){
            int i = im*64 + t;
            s += rs[i]; q += rq[i];
            lmn = min(lmn, rmn[i]); lmx = max(lmx, rmx[i]);
        }
        float2 pp; pp.x = s; pp.y = q;
        g_pp1[t*512 + blk] = pp;
        atomicMin(&g_cmn1[t], lmn); atomicMax(&g_cmx1[t], lmx);
    }
}

/* ---- fused fin1 + q1: one block, 1024 threads, float2 partials ---- */
__global__ void k_finq1(){
    int t = threadIdx.x;
    int c = t >> 4, sub = t & 15;
    float s = 0.f, q = 0.f;
    for (int i = sub; i < 512; i += 16){
        float2 pp = g_pp1[c*512 + i];
        s += pp.x; q += pp.y;
    }
    #pragma unroll
    for (int o = 8; o > 0; o >>= 1){
        s += __shfl_down_sync(0xFFFFFFFFu, s, o);
        q += __shfl_down_sync(0xFFFFFFFFu, q, o);
    }
    __shared__ float sbm[64], sbi[64];
    if (sub == 0){
        float N = (float)(BATCH*144);
        float m = s / N; float v = q / N - m*m;
        float iv = 1.0f / sqrtf(v + 1e-5f);
        g_bn1m[c] = m; g_bn1i[c] = iv;
        sbm[c] = m; sbi[c] = iv;
    }
    __syncthreads();
    __shared__ float smn[64], smx[64];
    if (t < 64){
        float m = sbm[t], iv = sbi[t];
        smn[t] = fmaxf(__fmul_rn(__fsub_rn(fdec(g_cmn1[t]), m), iv), 0.f);
        smx[t] = fmaxf(__fmul_rn(__fsub_rn(fdec(g_cmx1[t]), m), iv), 0.f);
    }
    __syncthreads();
    for (int o = 32; o > 0; o >>= 1){
        if (t < o){ smn[t] = fminf(smn[t], smn[t+o]); smx[t] = fmaxf(smx[t], smx[t+o]); }
        __syncthreads();
    }
    if (t == 0){ g_qmm[0] = smn[0]; g_qmm[1] = smx[0]; }
}

/* ---- conv2 fused, 640 threads (R13 form); blocks 0-1 run wgen L2/L3
        (w3t/w4, needed only by fc1/fc2) hidden under conv2's runtime ---- */
__global__ void __launch_bounds__(640, 1) k_conv2(const int* __restrict__ qb,
                      const float* s3,const float* g3,const float* a3,const float* b3,
                      const float* s4,const float* g4,const float* a4,const float* b4)
{
    extern __shared__ float sm[];
    int t = threadIdx.x;

    if (blockIdx.x < 2){
        /* wgen for L2 (n=51200 -> w3t) and L3 (n=1280 -> w4), 640 threads,
           smem carved from the dynamic allocation */
        int L = blockIdx.x + 2;
        const float *sc, *sg, *h1, *h0; int n; float coeff;
        if (L == 2){ sc=s3; sg=g3; h1=a3; h0=b3; n=51200; coeff=0.1f; }
        else       { sc=s4; sg=g4; h1=a4; h0=b4; n=1280;  coeff=0.17677669529663689f; }

        float* red = sm;                                   /* 1024 floats */
        unsigned* hist = (unsigned*)(sm + 1024);           /* 4*256       */
        int* ties = (int*)(sm + 2048);                     /* 2048        */
        unsigned* sh_pref = (unsigned*)(sm + 4096);
        int* sh_rank = (int*)(sm + 4097);
        int* ntie = (int*)(sm + 4098);
        int* Gtot = (int*)(sm + 4099);
        int* Cidx = (int*)(sm + 4100);
        int hg = (t >> 7) & 3;

        float s = 0.f;
        for (int i = t; i < n; i += 640) s += h1[i];
        red[t] = s;
        if (t < 384) red[640 + t] = 0.f;
        __syncthreads();
        for (int o = 512; o > 0; o >>= 1){ if (t < o) red[t] += red[t+o]; __syncthreads(); }
        if (t == 0) g_inv[L] = coeff / (red[0] / (float)n);

        unsigned pref = 0; int rank = n >> 1;
        for (int shift = 24; shift >= 0; shift -= 8){
            for (int i = t; i < 1024; i += 640) hist[i] = 0u;
            __syncthreads();
            unsigned mask = (shift < 24) ? (0xFFFFFFFFu << (shift+8)) : 0u;
            for (int i = t; i < n; i += 640){
                unsigned k = __float_as_uint(fabsf(sc[i]));
                if ((k & mask) == (pref & mask)) atomicAdd(&hist[hg*256 + ((k >> shift) & 255)], 1u);
            }
            __syncthreads();
            if (t == 0){
                unsigned c = 0; int d = 0;
                for (; d < 255; d++){
                    unsigned hd = hist[d]+hist[256+d]+hist[512+d]+hist[768+d];
                    if (c + hd > (unsigned)rank) break; c += hd;
                }
                *sh_pref = pref | ((unsigned)d << shift);
                *sh_rank = rank - (int)c;
            }
            __syncthreads();
            pref = *sh_pref; rank = *sh_rank;
            __syncthreads();
        }
        unsigned thr = pref;
        if (t == 0){ *ntie = 0; *Gtot = 0; }
        __syncthreads();
        int g = 0;
        for (int i = t; i < n; i += 640){
            unsigned k = __float_as_uint(fabsf(sc[i]));
            if (k > thr) g++;
            else if (k == thr){ int p = atomicAdd(ntie, 1); if (p < 2048) ties[p] = i; }
        }
        atomicAdd(Gtot, g);
        __syncthreads();
        if (t == 0){
            int E = *ntie; if (E > 2048) E = 2048;
            for (int a = 1; a < E; a++){
                int v = ties[a]; int b2 = a - 1;
                while (b2 >= 0 && ties[b2] > v){ ties[b2+1] = ties[b2]; b2--; }
                ties[b2+1] = v;
            }
            int T1 = (n - (n >> 1)) - *Gtot;
            if (T1 < 1) T1 = 1; if (T1 > E) T1 = E;
            *Cidx = ties[E - T1];
        }
        __syncthreads();
        int C = *Cidx;
        for (int i = t; i < n; i += 640){
            unsigned k = __float_as_uint(fabsf(sc[i]));
            bool m = (k > thr) || (k == thr && i >= C);
            float val = sg[i] * (m ? h1[i] : h0[i]);
            if (L == 2) g_w3t[(i % 400)*128 + (i / 400)] = val;
            else g_w4[i] = val;
        }
        return;
    }

    int blk = blockIdx.x - 2;   /* 0..1023, 4 images each */
    float* in2 = sm;                 /* 4*9216 = 36864 */
    float* ws  = sm + 36864;         /* 16*577 =  9232 */
    float* a0s = sm + 46096;         /* 4*196  =   784 */
    float* w1s = sm + 46880;         /* 576 -> 47456 floats */
    float mn = fdec(g_mm[0]), mx = fdec(g_mm[1]);
    float lv = (float)((1 << qb[0]) - 1);
    float sc = (mx - mn) / lv;
    float zp = floorf(mn / sc);
    float rsc = 1.0f / sc;
    for (int i = t; i < 784; i += 640)
        a0s[i] = QUANTA0(g_a0raw[blk*784 + i]);
    for (int i = t; i < 576; i += 640) w1s[i] = g_w1[i];
    __syncthreads();

    float qs1 = (g_qmm[1] - g_qmm[0]) / lv;
    float rq1 = 1.0f / qs1;
    if (t < 512){
        int img = t >> 7, co = (t >> 1) & 63, half = t & 1;
        u64 wp[9];
        #pragma unroll
        for (int k = 0; k < 9; k++){ float w = w1s[co*9 + k]; wp[k] = pack2(w, w); }
        float inv = g_inv[0];
        float m1 = g_bn1m[co], i1 = g_bn1i[co];
        const float* A = &a0s[img*196];
        float2* dst = (float2*)(in2 + img*9216 + co*144);
        int rb = half*6;

#define EMITB(PR) do{ _Pragma("unroll") for (int j = 0; j < 6; j++){ \
        float2 f = unpack2(acc[j]); \
        float y0 = __fmul_rn(f.x, inv), y1 = __fmul_rn(f.y, inv); \
        float u0 = fmaxf(__fmul_rn(__fsub_rn(y0, m1), i1), 0.f); \
        float u1 = fmaxf(__fmul_rn(__fsub_rn(y1, m1), i1), 0.f); \
        float2 o; \
        o.x = __fmul_rn(fminf(fmaxf(rintf(__fmul_rn(u0, rq1)), 0.f), lv), qs1); \
        o.y = __fmul_rn(fminf(fmaxf(rintf(__fmul_rn(u1, rq1)), 0.f), lv), qs1); \
        dst[(PR)*6 + j] = o; }}while(0)

        u64 R0[7], R1[7], R2[7];
        LOADROW(A, rb, R0); LOADROW(A, rb+1, R1);
        #pragma unroll
        for (int pr3 = 0; pr3 < 6; pr3 += 3){
            int base = rb + pr3;
            { LOADROW(A, base+2, R2); u64 acc[6];
              #pragma unroll
              for (int j=0;j<6;j++) acc[j]=pack2(0.f,0.f);
              C1ROW(R0, wp[0],wp[1],wp[2]); C1ROW(R1, wp[3],wp[4],wp[5]); C1ROW(R2, wp[6],wp[7],wp[8]);
              EMITB(base); }
            { LOADROW(A, base+3, R0); u64 acc[6];
              #pragma unroll
              for (int j=0;j<6;j++) acc[j]=pack2(0.f,0.f);
              C1ROW(R1, wp[0],wp[1],wp[2]); C1ROW(R2, wp[3],wp[4],wp[5]); C1ROW(R0, wp[6],wp[7],wp[8]);
              EMITB(base+1); }
            { LOADROW(A, base+4, R1); u64 acc[6];
              #pragma unroll
              for (int j=0;j<6;j++) acc[j]=pack2(0.f,0.f);
              C1ROW(R2, wp[0],wp[1],wp[2]); C1ROW(R0, wp[3],wp[4],wp[5]); C1ROW(R1, wp[6],wp[7],wp[8]);
              EMITB(base+2); }
        }
#undef EMITB
    } else {
        /* warps 16-19: stage w2 into ws, overlapped with phase B */
        for (int i = t - 512; i < 9216; i += 128)
            ws[(i/576)*577 + (i%576)] = g_w2[i];
    }
    __syncthreads();

    /* phase C: warp w=(img,hp); lane: co=lane>>1, cih=lane&1 (32 ci each) */
    int w = t >> 5, lane = t & 31;
    int img = w / 5, hp = w % 5;
    int co = lane >> 1, cih = lane & 1;
    const float4* base4 = (const float4*)(in2 + img*9216);
    u64 acc2[2][5], accO[2][6];
    u64 zz = pack2(0.f, 0.f);
    #pragma unroll
    for (int o = 0; o < 2; o++){
        #pragma unroll
        for (int p = 0; p < 5; p++) acc2[o][p] = zz;
        #pragma unroll
        for (int p = 0; p < 6; p++) accO[o][p] = zz;
    }

    #pragma unroll 1
    for (int cc = 0; cc < 32; cc++){
        int ci = cc*2 + cih;
        const float* wr = &ws[co*577 + ci*9];
        u64 wp2[3][3];
        #pragma unroll
        for (int kh = 0; kh < 3; kh++)
            #pragma unroll
            for (int kw = 0; kw < 3; kw++){ float wv = wr[kh*3+kw]; wp2[kh][kw] = pack2(wv, wv); }
        #pragma unroll
        for (int lr = 0; lr < 4; lr++){
            int row = hp*2 + lr;
            F4U u0, u1, u2;
            u0.f = base4[ci*36 + row*3 + 0];
            u1.f = base4[ci*36 + row*3 + 1];
            u2.f = base4[ci*36 + row*3 + 2];
            u64 E[6];
            E[0]=u0.u[0]; E[1]=u0.u[1]; E[2]=u1.u[0]; E[3]=u1.u[1]; E[4]=u2.u[0]; E[5]=u2.u[1];
            if (lr <= 2){
                int kh = lr;
                #pragma unroll
                for (int p = 0; p < 5; p++) fma2(acc2[0][p], E[p],   wp2[kh][0]);
                #pragma unroll
                for (int p = 0; p < 6; p++) fma2(accO[0][p], E[p],   wp2[kh][1]);
                #pragma unroll
                for (int p = 0; p < 5; p++) fma2(acc2[0][p], E[p+1], wp2[kh][2]);
            }
            if (lr >= 1){
                int kh = lr - 1;
                #pragma unroll
                for (int p = 0; p < 5; p++) fma2(acc2[1][p], E[p],   wp2[kh][0]);
                #pragma unroll
                for (int p = 0; p < 6; p++) fma2(accO[1][p], E[p],   wp2[kh][1]);
                #pragma unroll
                for (int p = 0; p < 5; p++) fma2(acc2[1][p], E[p+1], wp2[kh][2]);
            }
        }
    }

    #pragma unroll
    for (int o = 0; o < 2; o++)
        #pragma unroll
        for (int p = 0; p < 5; p++)
            acc2[o][p] = add2(acc2[o][p], mkO(accO[o][p], accO[o][p+1]));

    #pragma unroll
    for (int o = 0; o < 2; o++)
        #pragma unroll
        for (int p = 0; p < 5; p++){
            u64 other = __shfl_xor_sync(0xFFFFFFFFu, acc2[o][p], 1);
            acc2[o][p] = add2(acc2[o][p], other);
        }

    float inv2 = g_inv[1];
    float s5 = 0.f, q5 = 0.f;
    unsigned mn5 = 0xFFFFFFFFu, mx5 = 0u;
    int pid = img*80 + co*5 + hp;
    if (cih == 0){
        int bimg = blk*4 + img;
        float* dstp = &g_p2[(bimg*16 + co)*25 + hp*5];
        #pragma unroll
        for (int p = 0; p < 5; p++){
            float2 a0 = unpack2(acc2[0][p]), a1 = unpack2(acc2[1][p]);
            float v = fmaxf(fmaxf(a0.x, a0.y), fmaxf(a1.x, a1.y)) * inv2;
            dstp[p] = v;
            s5 += v; q5 = fmaf(v, v, q5);
            unsigned e = fenc(v);
            mn5 = min(mn5, e); mx5 = max(mx5, e);
        }
    }
    __syncthreads();
    float* s_s = sm; float* s_q = sm + 320;
    unsigned* s_mn = (unsigned*)(sm + 640); unsigned* s_mx = (unsigned*)(sm + 960);
    if (cih == 0){ s_s[pid] = s5; s_q[pid] = q5; s_mn[pid] = mn5; s_mx[pid] = mx5; }
    __syncthreads();
    float* c_s = sm + 1280; float* c_q = sm + 1344;
    unsigned* c_mn = (unsigned*)(sm + 1408); unsigned* c_mx = (unsigned*)(sm + 1472);
    if (t < 64){
        int im = t >> 4, c = t & 15;
        int base = im*80 + c*5;
        float s = 0.f, q = 0.f;
        unsigned lmn = 0xFFFFFFFFu, lmx = 0u;
        #pragma unroll
        for (int h = 0; h < 5; h++){
            s += s_s[base + h]; q += s_q[base + h];
            lmn = min(lmn, s_mn[base + h]);
            lmx = max(lmx, s_mx[base + h]);
        }
        c_s[t] = s; c_q[t] = q; c_mn[t] = lmn; c_mx[t] = lmx;
    }
    __syncthreads();
    if (t < 16){
        float s = 0.f, q = 0.f;
        unsigned lmn = 0xFFFFFFFFu, lmx = 0u;
        #pragma unroll
        for (int im = 0; im < 4; im++){
            int i = im*16 + t;
            s += c_s[i]; q += c_q[i];
            lmn = min(lmn, c_mn[i]); lmx = max(lmx, c_mx[i]);
        }
        float2 pp; pp.x = s; pp.y = q;
        g_pp2[t*1024 + blk] = pp;
        atomicMin(&g_cmn2[t], lmn); atomicMax(&g_cmx2[t], lmx);
    }
}

/* ---- fused fin2 + q2: one block, 256 threads, float2 partials ---- */
__global__ void k_finq2(){
    int t = threadIdx.x;
    int c = t >> 4, sub = t & 15;
    float s = 0.f, q = 0.f;
    for (int i = sub; i < 1024; i += 16){
        float2 pp = g_pp2[c*1024 + i];
        s += pp.x; q += pp.y;
    }
    #pragma unroll
    for (int o = 8; o > 0; o >>= 1){
        s += __shfl_down_sync(0xFFFFFFFFu, s, o);
        q += __shfl_down_sync(0xFFFFFFFFu, q, o);
    }
    __shared__ float sbm[16], sbi[16];
    if (sub == 0){
        float N = (float)(BATCH*25);
        float m = s / N; float v = q / N - m*m;
        float iv = 1.0f / sqrtf(v + 1e-5f);
        g_bn2m[c] = m; g_bn2i[c] = iv;
        sbm[c] = m; sbi[c] = iv;
    }
    __syncthreads();
    __shared__ float smn[16], smx[16];
    if (t < 16){
        float m = sbm[t], iv = sbi[t];
        smn[t] = fmaxf(__fmul_rn(__fsub_rn(fdec(g_cmn2[t]), m), iv), 0.f);
        smx[t] = fmaxf(__fmul_rn(__fsub_rn(fdec(g_cmx2[t]), m), iv), 0.f);
    }
    __syncthreads();
    for (int o = 8; o > 0; o >>= 1){
        if (t < o){ smn[t] = fminf(smn[t], smn[t+o]); smx[t] = fmaxf(smx[t], smx[t+o]); }
        __syncthreads();
    }
    if (t == 0){ g_qmm[2] = smn[0]; g_qmm[3] = smx[0]; }
}

/* ---- fc1 ---- */
__global__ void k_fc1(const int* __restrict__ qb){
    __shared__ float As[32][17];
    __shared__ float Bs[16][132];
    __shared__ unsigned smn, smx;
    int t = threadIdx.x;
    if (t == 0){ smn = 0xFFFFFFFFu; smx = 0u; }
    int rblk = blockIdx.x * 32;
    float lv = (float)((1 << qb[0]) - 1);
    float qs = (g_qmm[3] - g_qmm[2]) / lv;
    float rq = 1.0f / qs;
    float acc[4][4];
    #pragma unroll
    for (int i = 0; i < 4; i++)
        #pragma unroll
        for (int j = 0; j < 4; j++) acc[i][j] = 0.f;
    int rg = (t >> 5) * 4, c0 = t & 31;
    for (int kt = 0; kt < 400; kt += 16){
        for (int i = t; i < 512; i += 256){
            int row = i >> 4, kk = i & 15, k = kt + kk;
            int c = k / 25, rem = k % 25;
            float v = g_p2[((rblk + row)*16 + c)*25 + rem];
            float y = fmaxf(__fmul_rn(__fsub_rn(v, g_bn2m[c]), g_bn2i[c]), 0.f);
            As[row][kk] = fminf(fmaxf(rintf(y*rq), 0.f), lv) * qs;
        }
        for (int i = t; i < 2048; i += 256){
            int kk = i >> 7, nn = i & 127;
            Bs[kk][nn] = g_w3t[(kt + kk)*128 + nn];
        }
        __syncthreads();
        #pragma unroll
        for (int kk = 0; kk < 16; kk++){
            float a0 = As[rg][kk], a1 = As[rg+1][kk], a2 = As[rg+2][kk], a3 = As[rg+3][kk];
            float b0 = Bs[kk][c0], b1 = Bs[kk][c0+32], b2 = Bs[kk][c0+64], b3 = Bs[kk][c0+96];
            acc[0][0]=fmaf(a0,b0,acc[0][0]); acc[0][1]=fmaf(a0,b1,acc[0][1]);
            acc[0][2]=fmaf(a0,b2,acc[0][2]); acc[0][3]=fmaf(a0,b3,acc[0][3]);
            acc[1][0]=fmaf(a1,b0,acc[1][0]); acc[1][1]=fmaf(a1,b1,acc[1][1]);
            acc[1][2]=fmaf(a1,b2,acc[1][2]); acc[1][3]=fmaf(a1,b3,acc[1][3]);
            acc[2][0]=fmaf(a2,b0,acc[2][0]); acc[2][1]=fmaf(a2,b1,acc[2][1]);
            acc[2][2]=fmaf(a2,b2,acc[2][2]); acc[2][3]=fmaf(a2,b3,acc[2][3]);
            acc[3][0]=fmaf(a3,b0,acc[3][0]); acc[3][1]=fmaf(a3,b1,acc[3][1]);
            acc[3][2]=fmaf(a3,b2,acc[3][2]); acc[3][3]=fmaf(a3,b3,acc[3][3]);
        }
        __syncthreads();
    }
    float inv = g_inv[2];
    unsigned lmn = 0xFFFFFFFFu, lmx = 0u;
    #pragma unroll
    for (int ii = 0; ii < 4; ii++)
        #pragma unroll
        for (int jj = 0; jj < 4; jj++){
            float y = fmaxf(acc[ii][jj] * inv, 0.f);
            g_y3[(rblk + rg + ii)*128 + c0 + 32*jj] = y;
            unsigned e = fenc(y);
            lmn = min(lmn, e); lmx = max(lmx, e);
        }
    atomicMin(&smn, lmn); atomicMax(&smx, lmx);
    __syncthreads();
    if (t == 0){ atomicMin(&g_mm[6], smn); atomicMax(&g_mm[7], smx); }
}

/* ---- fc2 + log_softmax ---- */
__global__ void k_fc2(const int* __restrict__ qb, float* __restrict__ out){
    __shared__ float ws[1280];
    int t = threadIdx.x;
    for (int i = t; i < 1280; i += 256) ws[i] = g_w4[i];
    __syncthreads();
    float mn = fdec(g_mm[6]), mx = fdec(g_mm[7]);
    float lv = (float)((1 << qb[0]) - 1);
    float qs = (mx - mn) / lv;
    float rq = 1.0f / qs;
    float inv = g_inv[3];
    int warp = t / 32, lane = t % 32;
    int b = blockIdx.x * 8 + warp;
    float acc[10];
    #pragma unroll
    for (int o = 0; o < 10; o++) acc[o] = 0.f;
    for (int k = lane; k < 128; k += 32){
        float y = g_y3[b*128 + k];
        float q = fminf(fmaxf(rintf(y*rq), 0.f), lv) * qs;
        #pragma unroll
        for (int o = 0; o < 10; o++) acc[o] = fmaf(q, ws[o*128 + k], acc[o]);
    }
    #pragma unroll
    for (int off = 16; off > 0; off >>= 1)
        #pragma unroll
        for (int o = 0; o < 10; o++) acc[o] += __shfl_down_sync(0xFFFFFFFFu, acc[o], off);
    if (lane == 0){
        float l[10], m = -1e30f;
        #pragma unroll
        for (int o = 0; o < 10; o++){ l[o] = acc[o] * inv; m = fmaxf(m, l[o]); }
        float s = 0.f;
        #pragma unroll
        for (int o = 0; o < 10; o++) s += expf(l[o] - m);
        float ls = logf(s);
        #pragma unroll
        for (int o = 0; o < 10; o++) out[b*10 + o] = l[o] - m - ls;
    }
}

extern "C" void kernel_launch(void* const* d_in, const int* in_sizes, int n_in,
                              void* d_out, int out_size)
{
    const float* x   = (const float*)d_in[0];
    const float* sc1 = (const float*)d_in[1];
    const float* sg1 = (const float*)d_in[2];
    const float* h11 = (const float*)d_in[3];
    const float* h10 = (const float*)d_in[4];
    const float* sc2 = (const float*)d_in[5];
    const float* sg2 = (const float*)d_in[6];
    const float* h21 = (const float*)d_in[7];
    const float* h20 = (const float*)d_in[8];
    const float* sc3 = (const float*)d_in[9];
    const float* sg3 = (const float*)d_in[10];
    const float* h31 = (const float*)d_in[11];
    const float* h30 = (const float*)d_in[12];
    const float* sc4 = (const float*)d_in[13];
    const float* sg4 = (const float*)d_in[14];
    const float* h41 = (const float*)d_in[15];
    const float* h40 = (const float*)d_in[16];
    const int*   qb  = (const int*)d_in[17];
    float* out = (float*)d_out;

    cudaFuncSetAttribute(k_conv2, cudaFuncAttributeMaxDynamicSharedMemorySize, 189824);

    k_init<<<1, 128>>>();
    k_pre<<<2 + 392, 1024>>>(x,
                             sc1, sg1, h11, h10,
                             sc2, sg2, h21, h20);
    k_conv1s<<<512, 512>>>(qb);
    k_finq1<<<1, 1024>>>();
    k_conv2<<<1026, 640, 189824>>>(qb,
                                   sc3, sg3, h31, h30,
                                   sc4, sg4, h41, h40);
    k_finq2<<<1, 256>>>();
    k_fc1<<<128, 256>>>(qb);
    k_fc2<<<512, 256>>>(qb, out);
}